// round 1
// baseline (speedup 1.0000x reference)
#include <cuda_runtime.h>
#include <math.h>

#define NN 32768
#define XDIM 8
#define LL 16
#define DD 64
#define RR 64
#define HE 256
#define HN 512
#define MX 32
#define LOG2PI_F 1.8378770664093453f

#define PHI_T 128
#define PHI_B (NN / PHI_T)

// scratch (device globals: allocation-free contract)
__device__ float g_enc[(size_t)LL * NN * DD];    // 128 MB: encoder outputs per step
__device__ float g_XT[(size_t)LL * NN * XDIM];   // 16 MB: x transposed to [l][n][xd]
__device__ float g_tmp[2][(size_t)NN * RR];      // ping-pong recurrent state
__device__ float g_w2T[HN * RR];                 // nade_w2 transposed
__device__ float g_e2T[HE * DD];                 // enc2_w transposed
__device__ float g_npart[LL * PHI_B];            // per-block norm partials

// ---------------------------------------------------------------- prep
__global__ void prep_kernel(const float* __restrict__ e2w, const float* __restrict__ w2) {
    int idx = blockIdx.x * blockDim.x + threadIdx.x;   // 0..32767
    if (idx < HE * DD) { int e = idx / DD, d = idx % DD; g_e2T[idx] = e2w[d * HE + e]; }
    if (idx < HN * RR) { int e = idx / RR, j = idx % RR; g_w2T[idx] = w2[j * HN + e]; }
}

__global__ void init_kernel(const float* __restrict__ iw, float* __restrict__ out, int out_n) {
    int idx = blockIdx.x * blockDim.x + threadIdx.x;   // covers NN*RR
    if (idx < NN * RR) g_tmp[0][idx] = iw[idx & (RR - 1)];
    if (idx < out_n) out[idx] = 0.f;
}

// ---------------------------------------------------------------- encoder
// thread per (l, n): enc[d] = b2[d] + sum_e relu(b1[e] + w1[e,:]·x) * e2T[e][d]
__global__ __launch_bounds__(256) void enc_kernel(const float* __restrict__ X,
        const float* __restrict__ w1, const float* __restrict__ b1,
        const float* __restrict__ b2) {
    int id = blockIdx.x * 256 + threadIdx.x;
    int l = id & (LL - 1);
    int n = id >> 4;
    float x[XDIM];
#pragma unroll
    for (int k = 0; k < XDIM; k++) x[k] = X[((size_t)n * XDIM + k) * LL + l];
    float4* xt = (float4*)&g_XT[((size_t)l * NN + n) * XDIM];
    xt[0] = make_float4(x[0], x[1], x[2], x[3]);
    xt[1] = make_float4(x[4], x[5], x[6], x[7]);
    float acc[DD];
#pragma unroll
    for (int d = 0; d < DD; d++) acc[d] = 0.f;
    for (int e = 0; e < HE; e++) {
        const float4* w4 = (const float4*)&w1[e * XDIM];
        float4 wa = __ldg(&w4[0]);
        float4 wb = __ldg(&w4[1]);
        float h = __ldg(&b1[e]);
        h += wa.x * x[0] + wa.y * x[1] + wa.z * x[2] + wa.w * x[3];
        h += wb.x * x[4] + wb.y * x[5] + wb.z * x[6] + wb.w * x[7];
        h = fmaxf(h, 0.f);
        const float4* et = (const float4*)&g_e2T[e * DD];
#pragma unroll
        for (int q = 0; q < 16; q++) {
            float4 a = et[q];
            acc[4*q+0] += a.x * h; acc[4*q+1] += a.y * h;
            acc[4*q+2] += a.z * h; acc[4*q+3] += a.w * h;
        }
    }
    float4* o = (float4*)&g_enc[((size_t)l * NN + n) * DD];
#pragma unroll
    for (int q = 0; q < 16; q++) {
        o[q] = make_float4(acc[4*q+0] + __ldg(&b2[4*q+0]),
                           acc[4*q+1] + __ldg(&b2[4*q+1]),
                           acc[4*q+2] + __ldg(&b2[4*q+2]),
                           acc[4*q+3] + __ldg(&b2[4*q+3]));
    }
}

// ---------------------------------------------------------------- recurrence update
// tmp_out[n,j] = sum_i tmp[n,i] * (sum_d enc[n,d] * core[i,d,j])
// block: 64 samples x all 64 j. thread tile: 2 samples x 8 j.
__global__ __launch_bounds__(256) void update_kernel(const float* __restrict__ core,
                                                     int t, int par) {
    __shared__ __align__(16) float s_tmpT[RR][64];   // [i][s]
    __shared__ __align__(16) float s_encT[DD][64];   // [d][s]
    int tid = threadIdx.x;
    int sb = blockIdx.x * 64;
    const float4* tin4 = (const float4*)(g_tmp[par] + (size_t)sb * RR);
    const float4* enc4 = (const float4*)(g_enc + ((size_t)(t - 1) * NN + sb) * DD);
    float* tout = g_tmp[par ^ 1] + (size_t)sb * RR;

    for (int v = tid; v < 1024; v += 256) {
        int s = v >> 4, c = (v & 15) << 2;
        float4 a = tin4[v];
        s_tmpT[c + 0][s] = a.x; s_tmpT[c + 1][s] = a.y;
        s_tmpT[c + 2][s] = a.z; s_tmpT[c + 3][s] = a.w;
        float4 b = enc4[v];
        s_encT[c + 0][s] = b.x; s_encT[c + 1][s] = b.y;
        s_encT[c + 2][s] = b.z; s_encT[c + 3][s] = b.w;
    }
    __syncthreads();

    int jt = (tid & 7) << 3;     // output tile start (8 j's)
    int st = (tid >> 3) << 1;    // sample pair
    float acc0[8], acc1[8];
#pragma unroll
    for (int k = 0; k < 8; k++) { acc0[k] = 0.f; acc1[k] = 0.f; }

    for (int i = 0; i < RR; i++) {
        const float4* cr = (const float4*)(core + (size_t)i * DD * RR);
        float a0[8], a1[8];
#pragma unroll
        for (int k = 0; k < 8; k++) { a0[k] = 0.f; a1[k] = 0.f; }
#pragma unroll 16
        for (int d = 0; d < DD; d++) {
            float e0 = s_encT[d][st];
            float e1 = s_encT[d][st + 1];
            float4 c0 = __ldg(&cr[d * 16 + (jt >> 2)]);
            float4 c1 = __ldg(&cr[d * 16 + (jt >> 2) + 1]);
            a0[0] += e0 * c0.x; a0[1] += e0 * c0.y; a0[2] += e0 * c0.z; a0[3] += e0 * c0.w;
            a0[4] += e0 * c1.x; a0[5] += e0 * c1.y; a0[6] += e0 * c1.z; a0[7] += e0 * c1.w;
            a1[0] += e1 * c0.x; a1[1] += e1 * c0.y; a1[2] += e1 * c0.z; a1[3] += e1 * c0.w;
            a1[4] += e1 * c1.x; a1[5] += e1 * c1.y; a1[6] += e1 * c1.z; a1[7] += e1 * c1.w;
        }
        float t0 = s_tmpT[i][st];
        float t1 = s_tmpT[i][st + 1];
#pragma unroll
        for (int k = 0; k < 8; k++) { acc0[k] += t0 * a0[k]; acc1[k] += t1 * a1[k]; }
    }
    float* o0 = tout + (size_t)st * RR + jt;
    float* o1 = o0 + RR;
    *(float4*)&o0[0] = make_float4(acc0[0], acc0[1], acc0[2], acc0[3]);
    *(float4*)&o0[4] = make_float4(acc0[4], acc0[5], acc0[6], acc0[7]);
    *(float4*)&o1[0] = make_float4(acc1[0], acc1[1], acc1[2], acc1[3]);
    *(float4*)&o1[4] = make_float4(acc1[4], acc1[5], acc1[6], acc1[7]);
}

// ---------------------------------------------------------------- phi
__device__ __forceinline__ float dot64(const float* __restrict__ w, const float* h) {
    const float4* w4 = (const float4*)w;
    float s0 = 0.f, s1 = 0.f, s2 = 0.f, s3 = 0.f;
#pragma unroll
    for (int q = 0; q < 16; q++) {
        float4 a = __ldg(&w4[q]);
        s0 += a.x * h[4*q+0]; s1 += a.y * h[4*q+1];
        s2 += a.z * h[4*q+2]; s3 += a.w * h[4*q+3];
    }
    return (s0 + s1) + (s2 + s3);
}

__global__ __launch_bounds__(PHI_T) void phi_kernel(int t, int par,
        const float* __restrict__ w1, const float* __restrict__ b1,
        const float* __restrict__ b2,
        const float* __restrict__ muw, const float* __restrict__ mub,
        const float* __restrict__ sgw, const float* __restrict__ sgb,
        const float* __restrict__ alw, const float* __restrict__ alb,
        float* __restrict__ out) {
    int tid = threadIdx.x;
    int n = blockIdx.x * PHI_T + tid;

    float h[RR];
    const float4* t4 = (const float4*)(g_tmp[par] + (size_t)n * RR);
#pragma unroll
    for (int q = 0; q < 16; q++) {
        float4 a = t4[q];
        h[4*q+0] = a.x; h[4*q+1] = a.y; h[4*q+2] = a.z; h[4*q+3] = a.w;
    }
    // norm partial (deterministic block tree)
    float sq = 0.f;
#pragma unroll
    for (int k = 0; k < RR; k++) sq += h[k] * h[k];
    __shared__ float red[PHI_T];
    red[tid] = sq;
    __syncthreads();
    for (int off = PHI_T / 2; off > 0; off >>= 1) {
        if (tid < off) red[tid] += red[tid + off];
        __syncthreads();
    }
    if (tid == 0) g_npart[t * PHI_B + blockIdx.x] = red[0];

    float x[XDIM];
    {
        const float4* x4 = (const float4*)(g_XT + ((size_t)t * NN + n) * XDIM);
        float4 a = x4[0]; x[0] = a.x; x[1] = a.y; x[2] = a.z; x[3] = a.w;
        float4 b = x4[1]; x[4] = b.x; x[5] = b.y; x[6] = b.z; x[7] = b.w;
    }

    float h2[RR];
#pragma unroll
    for (int j = 0; j < RR; j++) h2[j] = 0.f;
    for (int e = 0; e < HN; e++) {
        float hh = __ldg(&b1[e]) + dot64(&w1[e * RR], h);
        hh = fmaxf(hh, 0.f);
        const float4* wt = (const float4*)&g_w2T[e * RR];
#pragma unroll
        for (int q = 0; q < 16; q++) {
            float4 a = wt[q];
            h2[4*q+0] += a.x * hh; h2[4*q+1] += a.y * hh;
            h2[4*q+2] += a.z * hh; h2[4*q+3] += a.w * hh;
        }
    }
#pragma unroll
    for (int j = 0; j < RR; j++) h2[j] = fmaxf(h2[j] + __ldg(&b2[j]), 0.f);

    float la[MX], tt[MX];
#pragma unroll 1
    for (int m = 0; m < MX; m++) {
        float al = __ldg(&alb[m]) + dot64(&alw[m * RR], h2);
        float clp = -0.5f * XDIM * LOG2PI_F;
#pragma unroll
        for (int q = 0; q < XDIM; q++) {
            int o = m * XDIM + q;
            float mu = __ldg(&mub[o]) + dot64(&muw[o * RR], h2);
            float ls = __ldg(&sgb[o]) + dot64(&sgw[o * RR], h2);
            float z = (x[q] - mu) * __expf(-ls);
            clp += -0.5f * z * z - ls;
        }
        la[m] = al;
        tt[m] = al + clp;
    }
    float m1 = -3.4e38f, m2 = -3.4e38f;
#pragma unroll
    for (int m = 0; m < MX; m++) { m1 = fmaxf(m1, la[m]); m2 = fmaxf(m2, tt[m]); }
    float s1 = 0.f, s2 = 0.f;
#pragma unroll
    for (int m = 0; m < MX; m++) { s1 += __expf(la[m] - m1); s2 += __expf(tt[m] - m2); }
    out[n] += (m2 + __logf(s2)) - (m1 + __logf(s1));
}

// ---------------------------------------------------------------- norm finish
__global__ void finish_kernel(float* __restrict__ out, int out_n) {
    __shared__ float red[256];
    int tid = threadIdx.x;
    float s = 0.f;
    for (int v = tid; v < LL * PHI_B; v += 256) s += g_npart[v];
    red[tid] = s;
    __syncthreads();
    for (int off = 128; off > 0; off >>= 1) {
        if (tid < off) red[tid] += red[tid + off];
        __syncthreads();
    }
    if (tid == 0) out[out_n - 1] = red[0];
}

// ---------------------------------------------------------------- launch
extern "C" void kernel_launch(void* const* d_in, const int* in_sizes, int n_in,
                              void* d_out, int out_size) {
    const float* X    = (const float*)d_in[0];
    const float* iw   = (const float*)d_in[1];
    const float* cores= (const float*)d_in[2];
    const float* e1w  = (const float*)d_in[3];
    const float* e1b  = (const float*)d_in[4];
    const float* e2w  = (const float*)d_in[5];
    const float* e2b  = (const float*)d_in[6];
    const float* nw1  = (const float*)d_in[7];
    const float* nb1  = (const float*)d_in[8];
    const float* nw2  = (const float*)d_in[9];
    const float* nb2  = (const float*)d_in[10];
    const float* muw  = (const float*)d_in[11];
    const float* mub  = (const float*)d_in[12];
    const float* sgw  = (const float*)d_in[13];
    const float* sgb  = (const float*)d_in[14];
    const float* alw  = (const float*)d_in[15];
    const float* alb  = (const float*)d_in[16];
    float* out = (float*)d_out;

    prep_kernel<<<128, 256>>>(e2w, nw2);
    init_kernel<<<(NN * RR) / 256, 256>>>(iw, out, out_size);
    enc_kernel<<<(LL * NN) / 256, 256>>>(X, e1w, e1b, e2b);

    phi_kernel<<<PHI_B, PHI_T>>>(0, 0, nw1, nb1, nb2, muw, mub, sgw, sgb, alw, alb, out);
    for (int t = 1; t < LL; t++) {
        update_kernel<<<NN / 64, 256>>>(cores + (size_t)(t - 1) * RR * DD * RR, t, (t - 1) & 1);
        phi_kernel<<<PHI_B, PHI_T>>>(t, t & 1, nw1, nb1, nb2, muw, mub, sgw, sgb, alw, alb, out);
    }
    finish_kernel<<<1, 256>>>(out, out_size);
}

// round 2
// speedup vs baseline: 1.0062x; 1.0062x over previous
#include <cuda_runtime.h>
#include <math.h>

#define NN 32768
#define XDIM 8
#define LL 16
#define DD 64
#define RR 64
#define HE 256
#define HN 512
#define MX 32
#define LOG2PI_F 1.8378770664093453f

#define PHI_T 128
#define PHI_B (NN / PHI_T)

// scratch (device globals: allocation-free contract)
__device__ float g_enc[(size_t)LL * NN * DD];    // 128 MB: encoder outputs per step
__device__ float g_XT[(size_t)LL * NN * XDIM];   // 16 MB: x transposed to [l][n][xd]
__device__ float g_tmp[2][(size_t)NN * RR];      // ping-pong recurrent state
__device__ float g_w2T[HN * RR];                 // nade_w2 transposed
__device__ float g_e2T[HE * DD];                 // enc2_w transposed
__device__ float g_npart[LL * PHI_B];            // per-block norm partials

// ---------------------------------------------------------------- prep
__global__ void prep_kernel(const float* __restrict__ e2w, const float* __restrict__ w2) {
    int idx = blockIdx.x * blockDim.x + threadIdx.x;   // 0..32767
    if (idx < HE * DD) { int e = idx / DD, d = idx % DD; g_e2T[idx] = e2w[d * HE + e]; }
    if (idx < HN * RR) { int e = idx / RR, j = idx % RR; g_w2T[idx] = w2[j * HN + e]; }
}

__global__ void init_kernel(const float* __restrict__ iw, float* __restrict__ out, int out_n) {
    int idx = blockIdx.x * blockDim.x + threadIdx.x;   // covers NN*RR
    if (idx < NN * RR) g_tmp[0][idx] = iw[idx & (RR - 1)];
    if (idx < out_n) out[idx] = 0.f;
}

// ---------------------------------------------------------------- encoder
// thread per (l, n): enc[d] = b2[d] + sum_e relu(b1[e] + w1[e,:]·x) * e2T[e][d]
__global__ __launch_bounds__(256) void enc_kernel(const float* __restrict__ X,
        const float* __restrict__ w1, const float* __restrict__ b1,
        const float* __restrict__ b2) {
    int id = blockIdx.x * 256 + threadIdx.x;
    int l = id & (LL - 1);
    int n = id >> 4;
    float x[XDIM];
#pragma unroll
    for (int k = 0; k < XDIM; k++) x[k] = X[((size_t)n * XDIM + k) * LL + l];
    float4* xt = (float4*)&g_XT[((size_t)l * NN + n) * XDIM];
    xt[0] = make_float4(x[0], x[1], x[2], x[3]);
    xt[1] = make_float4(x[4], x[5], x[6], x[7]);
    float acc[DD];
#pragma unroll
    for (int d = 0; d < DD; d++) acc[d] = 0.f;
    for (int e = 0; e < HE; e++) {
        const float4* w4 = (const float4*)&w1[e * XDIM];
        float4 wa = __ldg(&w4[0]);
        float4 wb = __ldg(&w4[1]);
        float h = __ldg(&b1[e]);
        h += wa.x * x[0] + wa.y * x[1] + wa.z * x[2] + wa.w * x[3];
        h += wb.x * x[4] + wb.y * x[5] + wb.z * x[6] + wb.w * x[7];
        h = fmaxf(h, 0.f);
        const float4* et = (const float4*)&g_e2T[e * DD];
#pragma unroll
        for (int q = 0; q < 16; q++) {
            float4 a = et[q];
            acc[4*q+0] += a.x * h; acc[4*q+1] += a.y * h;
            acc[4*q+2] += a.z * h; acc[4*q+3] += a.w * h;
        }
    }
    float4* o = (float4*)&g_enc[((size_t)l * NN + n) * DD];
#pragma unroll
    for (int q = 0; q < 16; q++) {
        o[q] = make_float4(acc[4*q+0] + __ldg(&b2[4*q+0]),
                           acc[4*q+1] + __ldg(&b2[4*q+1]),
                           acc[4*q+2] + __ldg(&b2[4*q+2]),
                           acc[4*q+3] + __ldg(&b2[4*q+3]));
    }
}

// ---------------------------------------------------------------- recurrence update
// tmp_out[n,j] = sum_i tmp[n,i] * (sum_d enc[n,d] * core[i,d,j])
// block: 64 samples x all 64 j. thread tile: 2 samples x 8 j.
__global__ __launch_bounds__(256) void update_kernel(const float* __restrict__ core,
                                                     int t, int par) {
    __shared__ __align__(16) float s_tmpT[RR][64];   // [i][s]
    __shared__ __align__(16) float s_encT[DD][64];   // [d][s]
    int tid = threadIdx.x;
    int sb = blockIdx.x * 64;
    const float4* tin4 = (const float4*)(g_tmp[par] + (size_t)sb * RR);
    const float4* enc4 = (const float4*)(g_enc + ((size_t)(t - 1) * NN + sb) * DD);
    float* tout = g_tmp[par ^ 1] + (size_t)sb * RR;

    for (int v = tid; v < 1024; v += 256) {
        int s = v >> 4, c = (v & 15) << 2;
        float4 a = tin4[v];
        s_tmpT[c + 0][s] = a.x; s_tmpT[c + 1][s] = a.y;
        s_tmpT[c + 2][s] = a.z; s_tmpT[c + 3][s] = a.w;
        float4 b = enc4[v];
        s_encT[c + 0][s] = b.x; s_encT[c + 1][s] = b.y;
        s_encT[c + 2][s] = b.z; s_encT[c + 3][s] = b.w;
    }
    __syncthreads();

    int jt = (tid & 7) << 3;     // output tile start (8 j's)
    int st = (tid >> 3) << 1;    // sample pair
    float acc0[8], acc1[8];
#pragma unroll
    for (int k = 0; k < 8; k++) { acc0[k] = 0.f; acc1[k] = 0.f; }

    for (int i = 0; i < RR; i++) {
        const float4* cr = (const float4*)(core + (size_t)i * DD * RR);
        float a0[8], a1[8];
#pragma unroll
        for (int k = 0; k < 8; k++) { a0[k] = 0.f; a1[k] = 0.f; }
#pragma unroll 16
        for (int d = 0; d < DD; d++) {
            float e0 = s_encT[d][st];
            float e1 = s_encT[d][st + 1];
            float4 c0 = __ldg(&cr[d * 16 + (jt >> 2)]);
            float4 c1 = __ldg(&cr[d * 16 + (jt >> 2) + 1]);
            a0[0] += e0 * c0.x; a0[1] += e0 * c0.y; a0[2] += e0 * c0.z; a0[3] += e0 * c0.w;
            a0[4] += e0 * c1.x; a0[5] += e0 * c1.y; a0[6] += e0 * c1.z; a0[7] += e0 * c1.w;
            a1[0] += e1 * c0.x; a1[1] += e1 * c0.y; a1[2] += e1 * c0.z; a1[3] += e1 * c0.w;
            a1[4] += e1 * c1.x; a1[5] += e1 * c1.y; a1[6] += e1 * c1.z; a1[7] += e1 * c1.w;
        }
        float t0 = s_tmpT[i][st];
        float t1 = s_tmpT[i][st + 1];
#pragma unroll
        for (int k = 0; k < 8; k++) { acc0[k] += t0 * a0[k]; acc1[k] += t1 * a1[k]; }
    }
    float* o0 = tout + (size_t)st * RR + jt;
    float* o1 = o0 + RR;
    *(float4*)&o0[0] = make_float4(acc0[0], acc0[1], acc0[2], acc0[3]);
    *(float4*)&o0[4] = make_float4(acc0[4], acc0[5], acc0[6], acc0[7]);
    *(float4*)&o1[0] = make_float4(acc1[0], acc1[1], acc1[2], acc1[3]);
    *(float4*)&o1[4] = make_float4(acc1[4], acc1[5], acc1[6], acc1[7]);
}

// ---------------------------------------------------------------- phi
__device__ __forceinline__ float dot64(const float* __restrict__ w, const float* h) {
    const float4* w4 = (const float4*)w;
    float s0 = 0.f, s1 = 0.f, s2 = 0.f, s3 = 0.f;
#pragma unroll
    for (int q = 0; q < 16; q++) {
        float4 a = __ldg(&w4[q]);
        s0 += a.x * h[4*q+0]; s1 += a.y * h[4*q+1];
        s2 += a.z * h[4*q+2]; s3 += a.w * h[4*q+3];
    }
    return (s0 + s1) + (s2 + s3);
}

__global__ __launch_bounds__(PHI_T) void phi_kernel(int t, int par,
        const float* __restrict__ w1, const float* __restrict__ b1,
        const float* __restrict__ b2,
        const float* __restrict__ muw, const float* __restrict__ mub,
        const float* __restrict__ sgw, const float* __restrict__ sgb,
        const float* __restrict__ alw, const float* __restrict__ alb,
        float* __restrict__ out) {
    int tid = threadIdx.x;
    int n = blockIdx.x * PHI_T + tid;

    float h[RR];
    const float4* t4 = (const float4*)(g_tmp[par] + (size_t)n * RR);
#pragma unroll
    for (int q = 0; q < 16; q++) {
        float4 a = t4[q];
        h[4*q+0] = a.x; h[4*q+1] = a.y; h[4*q+2] = a.z; h[4*q+3] = a.w;
    }
    // norm partial (deterministic block tree)
    float sq = 0.f;
#pragma unroll
    for (int k = 0; k < RR; k++) sq += h[k] * h[k];
    __shared__ float red[PHI_T];
    red[tid] = sq;
    __syncthreads();
    for (int off = PHI_T / 2; off > 0; off >>= 1) {
        if (tid < off) red[tid] += red[tid + off];
        __syncthreads();
    }
    if (tid == 0) g_npart[t * PHI_B + blockIdx.x] = red[0];

    float x[XDIM];
    {
        const float4* x4 = (const float4*)(g_XT + ((size_t)t * NN + n) * XDIM);
        float4 a = x4[0]; x[0] = a.x; x[1] = a.y; x[2] = a.z; x[3] = a.w;
        float4 b = x4[1]; x[4] = b.x; x[5] = b.y; x[6] = b.z; x[7] = b.w;
    }

    float h2[RR];
#pragma unroll
    for (int j = 0; j < RR; j++) h2[j] = 0.f;
    for (int e = 0; e < HN; e++) {
        float hh = __ldg(&b1[e]) + dot64(&w1[e * RR], h);
        hh = fmaxf(hh, 0.f);
        const float4* wt = (const float4*)&g_w2T[e * RR];
#pragma unroll
        for (int q = 0; q < 16; q++) {
            float4 a = wt[q];
            h2[4*q+0] += a.x * hh; h2[4*q+1] += a.y * hh;
            h2[4*q+2] += a.z * hh; h2[4*q+3] += a.w * hh;
        }
    }
#pragma unroll
    for (int j = 0; j < RR; j++) h2[j] = fmaxf(h2[j] + __ldg(&b2[j]), 0.f);

    float la[MX], tt[MX];
#pragma unroll 1
    for (int m = 0; m < MX; m++) {
        float al = __ldg(&alb[m]) + dot64(&alw[m * RR], h2);
        float clp = -0.5f * XDIM * LOG2PI_F;
#pragma unroll
        for (int q = 0; q < XDIM; q++) {
            int o = m * XDIM + q;
            float mu = __ldg(&mub[o]) + dot64(&muw[o * RR], h2);
            float ls = __ldg(&sgb[o]) + dot64(&sgw[o * RR], h2);
            float z = (x[q] - mu) * __expf(-ls);
            clp += -0.5f * z * z - ls;
        }
        la[m] = al;
        tt[m] = al + clp;
    }
    float m1 = -3.4e38f, m2 = -3.4e38f;
#pragma unroll
    for (int m = 0; m < MX; m++) { m1 = fmaxf(m1, la[m]); m2 = fmaxf(m2, tt[m]); }
    float s1 = 0.f, s2 = 0.f;
#pragma unroll
    for (int m = 0; m < MX; m++) { s1 += __expf(la[m] - m1); s2 += __expf(tt[m] - m2); }
    out[n] += (m2 + __logf(s2)) - (m1 + __logf(s1));
}

// ---------------------------------------------------------------- norm finish
__global__ void finish_kernel(float* __restrict__ out, int out_n) {
    __shared__ float red[256];
    int tid = threadIdx.x;
    float s = 0.f;
    for (int v = tid; v < LL * PHI_B; v += 256) s += g_npart[v];
    red[tid] = s;
    __syncthreads();
    for (int off = 128; off > 0; off >>= 1) {
        if (tid < off) red[tid] += red[tid + off];
        __syncthreads();
    }
    if (tid == 0) out[out_n - 1] = red[0];
}

// ---------------------------------------------------------------- launch
extern "C" void kernel_launch(void* const* d_in, const int* in_sizes, int n_in,
                              void* d_out, int out_size) {
    const float* X    = (const float*)d_in[0];
    const float* iw   = (const float*)d_in[1];
    const float* cores= (const float*)d_in[2];
    const float* e1w  = (const float*)d_in[3];
    const float* e1b  = (const float*)d_in[4];
    const float* e2w  = (const float*)d_in[5];
    const float* e2b  = (const float*)d_in[6];
    const float* nw1  = (const float*)d_in[7];
    const float* nb1  = (const float*)d_in[8];
    const float* nw2  = (const float*)d_in[9];
    const float* nb2  = (const float*)d_in[10];
    const float* muw  = (const float*)d_in[11];
    const float* mub  = (const float*)d_in[12];
    const float* sgw  = (const float*)d_in[13];
    const float* sgb  = (const float*)d_in[14];
    const float* alw  = (const float*)d_in[15];
    const float* alb  = (const float*)d_in[16];
    float* out = (float*)d_out;

    prep_kernel<<<128, 256>>>(e2w, nw2);
    init_kernel<<<(NN * RR) / 256, 256>>>(iw, out, out_size);
    enc_kernel<<<(LL * NN) / 256, 256>>>(X, e1w, e1b, e2b);

    phi_kernel<<<PHI_B, PHI_T>>>(0, 0, nw1, nb1, nb2, muw, mub, sgw, sgb, alw, alb, out);
    for (int t = 1; t < LL; t++) {
        update_kernel<<<NN / 64, 256>>>(cores + (size_t)(t - 1) * RR * DD * RR, t, (t - 1) & 1);
        phi_kernel<<<PHI_B, PHI_T>>>(t, t & 1, nw1, nb1, nb2, muw, mub, sgw, sgb, alw, alb, out);
    }
    finish_kernel<<<1, 256>>>(out, out_size);
}

// round 3
// speedup vs baseline: 2.1440x; 2.1308x over previous
#include <cuda_runtime.h>
#include <math.h>

#define NN 32768
#define XDIM 8
#define LL 16
#define DD 64
#define RR 64
#define HE 256
#define HN 512
#define MX 32
#define LOG2PI_F 1.8378770664093453f
#define PHI_B (NN / 64)
#define HEADW 544

// scratch (device globals: allocation-free contract)
__device__ float g_enc[(size_t)LL * NN * DD];
__device__ float g_XT[(size_t)LL * NN * XDIM];
__device__ float g_tmp[2][(size_t)NN * RR];
__device__ float g_w1T[RR * HN];      // nade_w1 transposed: [i][e]
__device__ float g_w2T[HN * RR];      // nade_w2 transposed: [e][j]
__device__ float g_e2T[HE * DD];      // enc2_w transposed
__device__ float g_headT[RR * HEADW]; // per j: mu(256), sig(256), alpha(32)
__device__ float g_npart[LL * PHI_B];

// ---------------------------------------------------------------- prep
__global__ void prep_kernel(const float* __restrict__ e2w,
                            const float* __restrict__ nw1,
                            const float* __restrict__ nw2,
                            const float* __restrict__ muw,
                            const float* __restrict__ sgw,
                            const float* __restrict__ alw) {
    int idx = blockIdx.x * blockDim.x + threadIdx.x;
    if (idx < HE * DD) { int e = idx / DD, d = idx % DD; g_e2T[idx] = e2w[d * HE + e]; }
    if (idx < RR * HN) { int i = idx / HN, e = idx % HN; g_w1T[idx] = nw1[e * RR + i]; }
    if (idx < HN * RR) { int e = idx / RR, j = idx % RR; g_w2T[idx] = nw2[j * HN + e]; }
    if (idx < RR * HEADW) {
        int j = idx / HEADW, o = idx % HEADW;
        float v;
        if (o < 256)      v = muw[o * RR + j];
        else if (o < 512) v = sgw[(o - 256) * RR + j];
        else              v = alw[(o - 512) * RR + j];
        g_headT[idx] = v;
    }
}

__global__ void init_kernel(const float* __restrict__ iw, float* __restrict__ out, int out_n) {
    int idx = blockIdx.x * blockDim.x + threadIdx.x;
    if (idx < NN * RR) g_tmp[0][idx] = iw[idx & (RR - 1)];
    if (idx < out_n) out[idx] = 0.f;
}

// ---------------------------------------------------------------- encoder
__global__ __launch_bounds__(256) void enc_kernel(const float* __restrict__ X,
        const float* __restrict__ w1, const float* __restrict__ b1,
        const float* __restrict__ b2) {
    int id = blockIdx.x * 256 + threadIdx.x;
    int l = id & (LL - 1);
    int n = id >> 4;
    float x[XDIM];
#pragma unroll
    for (int k = 0; k < XDIM; k++) x[k] = X[((size_t)n * XDIM + k) * LL + l];
    float4* xt = (float4*)&g_XT[((size_t)l * NN + n) * XDIM];
    xt[0] = make_float4(x[0], x[1], x[2], x[3]);
    xt[1] = make_float4(x[4], x[5], x[6], x[7]);
    float acc[DD];
#pragma unroll
    for (int d = 0; d < DD; d++) acc[d] = 0.f;
    for (int e = 0; e < HE; e++) {
        const float4* w4 = (const float4*)&w1[e * XDIM];
        float4 wa = __ldg(&w4[0]);
        float4 wb = __ldg(&w4[1]);
        float h = __ldg(&b1[e]);
        h += wa.x * x[0] + wa.y * x[1] + wa.z * x[2] + wa.w * x[3];
        h += wb.x * x[4] + wb.y * x[5] + wb.z * x[6] + wb.w * x[7];
        h = fmaxf(h, 0.f);
        const float4* et = (const float4*)&g_e2T[e * DD];
#pragma unroll
        for (int q = 0; q < 16; q++) {
            float4 a = et[q];
            acc[4*q+0] += a.x * h; acc[4*q+1] += a.y * h;
            acc[4*q+2] += a.z * h; acc[4*q+3] += a.w * h;
        }
    }
    float4* o = (float4*)&g_enc[((size_t)l * NN + n) * DD];
#pragma unroll
    for (int q = 0; q < 16; q++) {
        o[q] = make_float4(acc[4*q+0] + __ldg(&b2[4*q+0]),
                           acc[4*q+1] + __ldg(&b2[4*q+1]),
                           acc[4*q+2] + __ldg(&b2[4*q+2]),
                           acc[4*q+3] + __ldg(&b2[4*q+3]));
    }
}

// ---------------------------------------------------------------- recurrence update
// tmp_out[n,j] = sum_i tmp[n,i] * (sum_d enc[n,d] * core[i,d,j])
// block: 128 samples x 64 j. thread tile: 4 samples x 8 j.
#define UST 132
__global__ __launch_bounds__(256, 2) void update_kernel(const float* __restrict__ core,
                                                        int t, int par) {
    __shared__ float sT[RR][UST];   // [i][s]
    __shared__ float sE[DD][UST];   // [d][s]
    int tid = threadIdx.x;
    int sb = blockIdx.x * 128;
    const float4* tin4 = (const float4*)(g_tmp[par] + (size_t)sb * RR);
    const float4* enc4 = (const float4*)(g_enc + ((size_t)(t - 1) * NN + sb) * DD);
    float* tout = g_tmp[par ^ 1] + (size_t)sb * RR;

    for (int v = tid; v < 2048; v += 256) {
        int s = v >> 4, c = (v & 15) << 2;
        float4 a = tin4[v];
        sT[c + 0][s] = a.x; sT[c + 1][s] = a.y; sT[c + 2][s] = a.z; sT[c + 3][s] = a.w;
        float4 b = enc4[v];
        sE[c + 0][s] = b.x; sE[c + 1][s] = b.y; sE[c + 2][s] = b.z; sE[c + 3][s] = b.w;
    }
    __syncthreads();

    int jt = (tid & 7) << 3;
    int sg = tid >> 3;              // local samples sg*4 .. sg*4+3
    float acc[4][8];
#pragma unroll
    for (int u = 0; u < 4; u++)
#pragma unroll
        for (int k = 0; k < 8; k++) acc[u][k] = 0.f;

    for (int i = 0; i < RR; i++) {
        float4 tv = *(const float4*)&sT[i][sg << 2];
        float a[4][8];
#pragma unroll
        for (int u = 0; u < 4; u++)
#pragma unroll
            for (int k = 0; k < 8; k++) a[u][k] = 0.f;
        const float4* cr = (const float4*)(core + (size_t)i * DD * RR + jt);
#pragma unroll 16
        for (int d = 0; d < DD; d++) {
            float4 ev = *(const float4*)&sE[d][sg << 2];
            float4 c0 = __ldg(cr + d * 16);
            float4 c1 = __ldg(cr + d * 16 + 1);
            float ee[4] = {ev.x, ev.y, ev.z, ev.w};
            float cc[8] = {c0.x, c0.y, c0.z, c0.w, c1.x, c1.y, c1.z, c1.w};
#pragma unroll
            for (int u = 0; u < 4; u++)
#pragma unroll
                for (int k = 0; k < 8; k++) a[u][k] = fmaf(ee[u], cc[k], a[u][k]);
        }
        float tt[4] = {tv.x, tv.y, tv.z, tv.w};
#pragma unroll
        for (int u = 0; u < 4; u++)
#pragma unroll
            for (int k = 0; k < 8; k++) acc[u][k] = fmaf(tt[u], a[u][k], acc[u][k]);
    }
#pragma unroll
    for (int u = 0; u < 4; u++) {
        float* o = tout + (size_t)((sg << 2) + u) * RR + jt;
        *(float4*)&o[0] = make_float4(acc[u][0], acc[u][1], acc[u][2], acc[u][3]);
        *(float4*)&o[4] = make_float4(acc[u][4], acc[u][5], acc[u][6], acc[u][7]);
    }
}

// ---------------------------------------------------------------- phi
__device__ __forceinline__ void lse_upd(float& M, float& S, float v) {
    float Mn = fmaxf(M, v);
    S = S * __expf(M - Mn) + __expf(v - Mn);
    M = Mn;
}

__global__ __launch_bounds__(256, 2) void phi_kernel(int t, int par,
        const float* __restrict__ b1, const float* __restrict__ b2,
        const float* __restrict__ mub, const float* __restrict__ sgb,
        const float* __restrict__ alb, float* __restrict__ out) {
    __shared__ float sT[RR][65];     // tmp transposed [i][s]
    __shared__ float sH1[RR][65];    // hidden1 chunk [e][s]
    __shared__ float sH2[RR][66];    // hidden2 [j][s]
    __shared__ float sred[256];
    __shared__ float lred[8][32][8];
    int tid = threadIdx.x;
    int bs = blockIdx.x * 64;

    // load tmp transposed + norm partial
    const float4* t4 = (const float4*)(g_tmp[par] + (size_t)bs * RR);
    float sq = 0.f;
    for (int v = tid; v < 1024; v += 256) {
        int s = v >> 4, c = (v & 15) << 2;
        float4 a = t4[v];
        sq += a.x * a.x + a.y * a.y + a.z * a.z + a.w * a.w;
        sT[c + 0][s] = a.x; sT[c + 1][s] = a.y; sT[c + 2][s] = a.z; sT[c + 3][s] = a.w;
    }
    sred[tid] = sq;
    __syncthreads();
    for (int off = 128; off > 0; off >>= 1) {
        if (tid < off) sred[tid] += sred[tid + off];
        __syncthreads();
    }
    if (tid == 0) g_npart[t * PHI_B + blockIdx.x] = sred[0];

    int et = (tid & 7) << 3;       // 8-wide output tile (e in stage1, j in stage2)
    int st = (tid >> 3) << 1;      // 2-sample pair
    float acc0[8], acc1[8];
#pragma unroll
    for (int k = 0; k < 8; k++) { acc0[k] = 0.f; acc1[k] = 0.f; }

    for (int c = 0; c < 8; c++) {
        // stage 1: h1[e] = relu(b1 + sum_i tmp[i] * w1T[i][e]) for 64 e's of chunk c
        float a0[8], a1[8];
#pragma unroll
        for (int k = 0; k < 8; k++) { a0[k] = 0.f; a1[k] = 0.f; }
#pragma unroll 8
        for (int i = 0; i < RR; i++) {
            float t0 = sT[i][st], t1 = sT[i][st + 1];
            const float4* wp = (const float4*)(g_w1T + i * HN + c * 64 + et);
            float4 w0 = __ldg(wp);
            float4 w1v = __ldg(wp + 1);
            float ww[8] = {w0.x, w0.y, w0.z, w0.w, w1v.x, w1v.y, w1v.z, w1v.w};
#pragma unroll
            for (int k = 0; k < 8; k++) {
                a0[k] = fmaf(t0, ww[k], a0[k]);
                a1[k] = fmaf(t1, ww[k], a1[k]);
            }
        }
        {
            const float4* bp = (const float4*)(b1 + c * 64 + et);
            float4 bb0 = __ldg(bp), bb1 = __ldg(bp + 1);
            float bb[8] = {bb0.x, bb0.y, bb0.z, bb0.w, bb1.x, bb1.y, bb1.z, bb1.w};
#pragma unroll
            for (int k = 0; k < 8; k++) {
                sH1[et + k][st]     = fmaxf(a0[k] + bb[k], 0.f);
                sH1[et + k][st + 1] = fmaxf(a1[k] + bb[k], 0.f);
            }
        }
        __syncthreads();
        // stage 2: h2[j] += sum_e h1[e] * w2T[e][j]
#pragma unroll 8
        for (int e = 0; e < RR; e++) {
            float h0 = sH1[e][st], h1 = sH1[e][st + 1];
            const float4* wp = (const float4*)(g_w2T + (size_t)(c * 64 + e) * RR + et);
            float4 w0 = __ldg(wp);
            float4 w1v = __ldg(wp + 1);
            float ww[8] = {w0.x, w0.y, w0.z, w0.w, w1v.x, w1v.y, w1v.z, w1v.w};
#pragma unroll
            for (int k = 0; k < 8; k++) {
                acc0[k] = fmaf(h0, ww[k], acc0[k]);
                acc1[k] = fmaf(h1, ww[k], acc1[k]);
            }
        }
        __syncthreads();
    }
    {
        const float4* bp = (const float4*)(b2 + et);
        float4 bb0 = __ldg(bp), bb1 = __ldg(bp + 1);
        float bb[8] = {bb0.x, bb0.y, bb0.z, bb0.w, bb1.x, bb1.y, bb1.z, bb1.w};
#pragma unroll
        for (int k = 0; k < 8; k++) {
            sH2[et + k][st]     = fmaxf(acc0[k] + bb[k], 0.f);
            sH2[et + k][st + 1] = fmaxf(acc1[k] + bb[k], 0.f);
        }
    }
    __syncthreads();

    // head: warp wg owns mixtures wg*4..wg*4+3; lane owns samples 2*lane, 2*lane+1
    int lane = tid & 31, wg = tid >> 5;
    int s0 = lane << 1;
    float x0[8], x1[8];
    {
        const float4* xp = (const float4*)(g_XT + ((size_t)t * NN + bs + s0) * XDIM);
        float4 xa = xp[0], xb = xp[1], xc = xp[2], xd = xp[3];
        x0[0] = xa.x; x0[1] = xa.y; x0[2] = xa.z; x0[3] = xa.w;
        x0[4] = xb.x; x0[5] = xb.y; x0[6] = xb.z; x0[7] = xb.w;
        x1[0] = xc.x; x1[1] = xc.y; x1[2] = xc.z; x1[3] = xc.w;
        x1[4] = xd.x; x1[5] = xd.y; x1[6] = xd.z; x1[7] = xd.w;
    }
    float mla0 = -3.4e38f, sla0 = 0.f, mtt0 = -3.4e38f, stt0 = 0.f;
    float mla1 = -3.4e38f, sla1 = 0.f, mtt1 = -3.4e38f, stt1 = 0.f;

#pragma unroll 1
    for (int mi = 0; mi < 4; mi++) {
        int m = (wg << 2) + mi;
        float mu0[8], mu1[8], ls0[8], ls1[8];
        float al0 = 0.f, al1 = 0.f;
#pragma unroll
        for (int q = 0; q < 8; q++) { mu0[q] = 0.f; mu1[q] = 0.f; ls0[q] = 0.f; ls1[q] = 0.f; }
#pragma unroll 4
        for (int j = 0; j < RR; j++) {
            float2 h = *(const float2*)&sH2[j][s0];
            const float4* row = (const float4*)(g_headT + j * HEADW);
            float4 wm0 = __ldg(row + (m << 1));
            float4 wm1 = __ldg(row + (m << 1) + 1);
            float4 ws0 = __ldg(row + 64 + (m << 1));
            float4 ws1 = __ldg(row + 64 + (m << 1) + 1);
            float wa = __ldg(g_headT + j * HEADW + 512 + m);
            float wm[8] = {wm0.x, wm0.y, wm0.z, wm0.w, wm1.x, wm1.y, wm1.z, wm1.w};
            float ws[8] = {ws0.x, ws0.y, ws0.z, ws0.w, ws1.x, ws1.y, ws1.z, ws1.w};
#pragma unroll
            for (int q = 0; q < 8; q++) {
                mu0[q] = fmaf(h.x, wm[q], mu0[q]);
                mu1[q] = fmaf(h.y, wm[q], mu1[q]);
                ls0[q] = fmaf(h.x, ws[q], ls0[q]);
                ls1[q] = fmaf(h.y, ws[q], ls1[q]);
            }
            al0 = fmaf(h.x, wa, al0);
            al1 = fmaf(h.y, wa, al1);
        }
        {
            const float4* mp = (const float4*)(mub + (m << 3));
            const float4* sp = (const float4*)(sgb + (m << 3));
            float4 m0 = __ldg(mp), m1 = __ldg(mp + 1);
            float4 sg0 = __ldg(sp), sg1 = __ldg(sp + 1);
            float mbv[8] = {m0.x, m0.y, m0.z, m0.w, m1.x, m1.y, m1.z, m1.w};
            float sbv[8] = {sg0.x, sg0.y, sg0.z, sg0.w, sg1.x, sg1.y, sg1.z, sg1.w};
            float alB = __ldg(alb + m);
            al0 += alB; al1 += alB;
            float clp0 = -0.5f * XDIM * LOG2PI_F;
            float clp1 = -0.5f * XDIM * LOG2PI_F;
#pragma unroll
            for (int q = 0; q < 8; q++) {
                float lq0 = ls0[q] + sbv[q];
                float lq1 = ls1[q] + sbv[q];
                float z0 = (x0[q] - (mu0[q] + mbv[q])) * __expf(-lq0);
                float z1 = (x1[q] - (mu1[q] + mbv[q])) * __expf(-lq1);
                clp0 += -0.5f * z0 * z0 - lq0;
                clp1 += -0.5f * z1 * z1 - lq1;
            }
            float tt0 = al0 + clp0, tt1 = al1 + clp1;
            lse_upd(mla0, sla0, al0); lse_upd(mtt0, stt0, tt0);
            lse_upd(mla1, sla1, al1); lse_upd(mtt1, stt1, tt1);
        }
    }
    lred[wg][lane][0] = mla0; lred[wg][lane][1] = sla0;
    lred[wg][lane][2] = mtt0; lred[wg][lane][3] = stt0;
    lred[wg][lane][4] = mla1; lred[wg][lane][5] = sla1;
    lred[wg][lane][6] = mtt1; lred[wg][lane][7] = stt1;
    __syncthreads();
    if (tid < 64) {
        int ln = tid >> 1, hf = (tid & 1) << 2;
        float M1 = -3.4e38f, S1 = 0.f, M2 = -3.4e38f, S2 = 0.f;
#pragma unroll
        for (int k = 0; k < 8; k++) {
            float gm = lred[k][ln][hf], gs = lred[k][ln][hf + 1];
            float Mn = fmaxf(M1, gm);
            S1 = S1 * __expf(M1 - Mn) + gs * __expf(gm - Mn);
            M1 = Mn;
            gm = lred[k][ln][hf + 2]; gs = lred[k][ln][hf + 3];
            Mn = fmaxf(M2, gm);
            S2 = S2 * __expf(M2 - Mn) + gs * __expf(gm - Mn);
            M2 = Mn;
        }
        out[bs + tid] += (M2 + __logf(S2)) - (M1 + __logf(S1));
    }
}

// ---------------------------------------------------------------- norm finish
__global__ void finish_kernel(float* __restrict__ out, int out_n) {
    __shared__ float red[256];
    int tid = threadIdx.x;
    float s = 0.f;
    for (int v = tid; v < LL * PHI_B; v += 256) s += g_npart[v];
    red[tid] = s;
    __syncthreads();
    for (int off = 128; off > 0; off >>= 1) {
        if (tid < off) red[tid] += red[tid + off];
        __syncthreads();
    }
    if (tid == 0) out[out_n - 1] = red[0];
}

// ---------------------------------------------------------------- launch
extern "C" void kernel_launch(void* const* d_in, const int* in_sizes, int n_in,
                              void* d_out, int out_size) {
    const float* X    = (const float*)d_in[0];
    const float* iw   = (const float*)d_in[1];
    const float* cores= (const float*)d_in[2];
    const float* e1w  = (const float*)d_in[3];
    const float* e1b  = (const float*)d_in[4];
    const float* e2w  = (const float*)d_in[5];
    const float* e2b  = (const float*)d_in[6];
    const float* nw1  = (const float*)d_in[7];
    const float* nb1  = (const float*)d_in[8];
    const float* nw2  = (const float*)d_in[9];
    const float* nb2  = (const float*)d_in[10];
    const float* muw  = (const float*)d_in[11];
    const float* mub  = (const float*)d_in[12];
    const float* sgw  = (const float*)d_in[13];
    const float* sgb  = (const float*)d_in[14];
    const float* alw  = (const float*)d_in[15];
    const float* alb  = (const float*)d_in[16];
    float* out = (float*)d_out;

    prep_kernel<<<(RR * HEADW + 255) / 256, 256>>>(e2w, nw1, nw2, muw, sgw, alw);
    init_kernel<<<(NN * RR) / 256, 256>>>(iw, out, out_size);
    enc_kernel<<<(LL * NN) / 256, 256>>>(X, e1w, e1b, e2b);

    phi_kernel<<<PHI_B, 256>>>(0, 0, nb1, nb2, mub, sgb, alb, out);
    for (int t = 1; t < LL; t++) {
        update_kernel<<<NN / 128, 256>>>(cores + (size_t)(t - 1) * RR * DD * RR, t, (t - 1) & 1);
        phi_kernel<<<PHI_B, 256>>>(t, t & 1, nb1, nb2, mub, sgb, alb, out);
    }
    finish_kernel<<<1, 256>>>(out, out_size);
}

// round 10
// speedup vs baseline: 4.2221x; 1.9693x over previous
#include <cuda_runtime.h>
#include <cuda_bf16.h>
#include <cstdint>
#include <math.h>

#define NN 32768
#define XDIM 8
#define LL 16
#define DD 64
#define RR 64
#define HE 256
#define HN 512
#define MX 32
#define LOG2PI_F 1.8378770664093453f
#define PHI_B (NN / 128)
#define HEADW 544
#define PHI_SMEM (3 * 64 * 132 * 4)

// scratch (device globals: allocation-free contract)
__device__ float g_enc[(size_t)LL * NN * DD];
__device__ float g_XT[(size_t)LL * NN * XDIM];
__device__ float g_tmp[2][(size_t)NN * RR];
__device__ float g_w1T[RR * HN];
__device__ float g_w2T[HN * RR];
__device__ float g_e2T[HE * DD];
__device__ float g_headT[RR * HEADW];
__device__ float g_npart[LL * PHI_B];
// B fragments, mma-ready: [15 steps][256 kiters][8 ntiles][32 lanes] of {b0hi,b1hi,b0lo,b1lo}
__device__ uint4 g_Bfrag[(size_t)(LL - 1) * 256 * 8 * 32];

// ---------------------------------------------------------------- helpers
__device__ __forceinline__ uint32_t pack_hi2(float lo_elem, float hi_elem) {
    // bf16 truncation of both, low half <- lo_elem
    return __byte_perm(__float_as_uint(lo_elem), __float_as_uint(hi_elem), 0x7632);
}
__device__ __forceinline__ uint32_t pack_rn2(float lo_elem, float hi_elem) {
    uint32_t r;
    asm("cvt.rn.bf16x2.f32 %0, %1, %2;" : "=r"(r) : "f"(hi_elem), "f"(lo_elem));
    return r;
}
__device__ __forceinline__ float trunc_bf(float v) {
    return __uint_as_float(__float_as_uint(v) & 0xFFFF0000u);
}
__device__ __forceinline__ void mma_bf16(float* c,
        uint32_t a0, uint32_t a1, uint32_t a2, uint32_t a3,
        uint32_t b0, uint32_t b1) {
    asm volatile(
        "mma.sync.aligned.m16n8k16.row.col.f32.bf16.bf16.f32 "
        "{%0,%1,%2,%3}, {%4,%5,%6,%7}, {%8,%9}, {%0,%1,%2,%3};"
        : "+f"(c[0]), "+f"(c[1]), "+f"(c[2]), "+f"(c[3])
        : "r"(a0), "r"(a1), "r"(a2), "r"(a3), "r"(b0), "r"(b1));
}

// ---------------------------------------------------------------- prep
__global__ void prep_kernel(const float* __restrict__ e2w,
                            const float* __restrict__ nw1,
                            const float* __restrict__ nw2,
                            const float* __restrict__ muw,
                            const float* __restrict__ sgw,
                            const float* __restrict__ alw) {
    int idx = blockIdx.x * blockDim.x + threadIdx.x;
    if (idx < HE * DD) { int e = idx / DD, d = idx % DD; g_e2T[idx] = e2w[d * HE + e]; }
    if (idx < RR * HN) { int i = idx / HN, e = idx % HN; g_w1T[idx] = nw1[e * RR + i]; }
    if (idx < HN * RR) { int e = idx / RR, j = idx % RR; g_w2T[idx] = nw2[j * HN + e]; }
    if (idx < RR * HEADW) {
        int j = idx / HEADW, o = idx % HEADW;
        float v;
        if (o < 256)      v = muw[o * RR + j];
        else if (o < 512) v = sgw[(o - 256) * RR + j];
        else              v = alw[(o - 512) * RR + j];
        g_headT[idx] = v;
    }
}

// Pack cores into per-lane mma B fragments.
// B[k][n] = cores[l*262144 + k*64 + n], k=(i,d), n=j.  Lane (g,tq): n = nt*8+g, k0 = ki*16+2tq.
__global__ void prep_bfrag_kernel(const float* __restrict__ cores) {
    int idx = blockIdx.x * blockDim.x + threadIdx.x;
    if (idx >= (LL - 1) * 256 * 8 * 32) return;
    int lane = idx & 31;
    int nt = (idx >> 5) & 7;
    int ki = (idx >> 8) & 255;
    int l = idx >> 16;
    int g = lane >> 2, tq = lane & 3;
    int n = nt * 8 + g;
    int k0 = ki * 16 + 2 * tq;
    const float* base = cores + (size_t)l * 262144 + (size_t)k0 * 64 + n;
    float v00 = base[0], v01 = base[64], v10 = base[512], v11 = base[576];
    uint4 r;
    r.x = pack_hi2(v00, v01);
    r.y = pack_hi2(v10, v11);
    r.z = pack_rn2(v00 - trunc_bf(v00), v01 - trunc_bf(v01));
    r.w = pack_rn2(v10 - trunc_bf(v10), v11 - trunc_bf(v11));
    g_Bfrag[idx] = r;
}

__global__ void init_kernel(const float* __restrict__ iw, float* __restrict__ out, int out_n) {
    int idx = blockIdx.x * blockDim.x + threadIdx.x;
    if (idx < NN * RR) g_tmp[0][idx] = iw[idx & (RR - 1)];
    if (idx < out_n) out[idx] = 0.f;
}

// ---------------------------------------------------------------- encoder
__global__ __launch_bounds__(256) void enc_kernel(const float* __restrict__ X,
        const float* __restrict__ w1, const float* __restrict__ b1,
        const float* __restrict__ b2) {
    int id = blockIdx.x * 256 + threadIdx.x;
    int l = id & (LL - 1);
    int n = id >> 4;
    float x[XDIM];
#pragma unroll
    for (int k = 0; k < XDIM; k++) x[k] = X[((size_t)n * XDIM + k) * LL + l];
    float4* xt = (float4*)&g_XT[((size_t)l * NN + n) * XDIM];
    xt[0] = make_float4(x[0], x[1], x[2], x[3]);
    xt[1] = make_float4(x[4], x[5], x[6], x[7]);
    float acc[DD];
#pragma unroll
    for (int d = 0; d < DD; d++) acc[d] = 0.f;
    for (int e = 0; e < HE; e++) {
        const float4* w4 = (const float4*)&w1[e * XDIM];
        float4 wa = __ldg(&w4[0]);
        float4 wb = __ldg(&w4[1]);
        float h = __ldg(&b1[e]);
        h += wa.x * x[0] + wa.y * x[1] + wa.z * x[2] + wa.w * x[3];
        h += wb.x * x[4] + wb.y * x[5] + wb.z * x[6] + wb.w * x[7];
        h = fmaxf(h, 0.f);
        const float4* et = (const float4*)&g_e2T[e * DD];
#pragma unroll
        for (int q = 0; q < 16; q++) {
            float4 a = et[q];
            acc[4*q+0] += a.x * h; acc[4*q+1] += a.y * h;
            acc[4*q+2] += a.z * h; acc[4*q+3] += a.w * h;
        }
    }
    float4* o = (float4*)&g_enc[((size_t)l * NN + n) * DD];
#pragma unroll
    for (int q = 0; q < 16; q++) {
        o[q] = make_float4(acc[4*q+0] + __ldg(&b2[4*q+0]),
                           acc[4*q+1] + __ldg(&b2[4*q+1]),
                           acc[4*q+2] + __ldg(&b2[4*q+2]),
                           acc[4*q+3] + __ldg(&b2[4*q+3]));
    }
}

// ---------------------------------------------------------------- recurrence update (mma.sync bf16)
// out[n,j] = sum_{k=(i,d)} A[n,k]*B[k,j], A built in registers as tmp[n,i]*enc[n,d].
// 3-term split: AhiBhi + AhiBlo + AloBhi. CTA = 128 rows, 8 warps x 16 rows, full N=64 per warp.
__global__ __launch_bounds__(256, 2) void update_mma_kernel(int t, int par) {
    __shared__ float sTmp[128][68];
    int tid = threadIdx.x;
    int wid = tid >> 5, lane = tid & 31;
    int g = lane >> 2, tq = lane & 3;
    int sb = blockIdx.x * 128;
    int r0 = wid * 16 + g, r1 = r0 + 8;

    // stage tmp (row-major) in smem
    const float4* tin4 = (const float4*)(g_tmp[par] + (size_t)sb * RR);
    for (int v = tid; v < 2048; v += 256) {
        int r = v >> 4, c = (v & 15) << 2;
        *(float4*)&sTmp[r][c] = tin4[v];
    }
    // enc values this thread needs, in registers: e[row][q][c], cols q*16 + 2tq + {0,1,8,9}
    float e0[4][4], e1[4][4];
    {
        const float* ep0 = g_enc + ((size_t)(t - 1) * NN + sb + r0) * DD;
        const float* ep1 = g_enc + ((size_t)(t - 1) * NN + sb + r1) * DD;
#pragma unroll
        for (int q = 0; q < 4; q++) {
            float2 a = __ldg((const float2*)(ep0 + q * 16 + 2 * tq));
            float2 b = __ldg((const float2*)(ep0 + q * 16 + 2 * tq + 8));
            e0[q][0] = a.x; e0[q][1] = a.y; e0[q][2] = b.x; e0[q][3] = b.y;
            float2 c = __ldg((const float2*)(ep1 + q * 16 + 2 * tq));
            float2 d = __ldg((const float2*)(ep1 + q * 16 + 2 * tq + 8));
            e1[q][0] = c.x; e1[q][1] = c.y; e1[q][2] = d.x; e1[q][3] = d.y;
        }
    }
    __syncthreads();

    float acc[8][4];
#pragma unroll
    for (int nt = 0; nt < 8; nt++)
#pragma unroll
        for (int c = 0; c < 4; c++) acc[nt][c] = 0.f;

    const uint4* bfr = g_Bfrag + (size_t)(t - 1) * 65536 + lane;

    for (int i = 0; i < 64; i++) {
        float t0 = sTmp[r0][i];
        float t1 = sTmp[r1][i];
#pragma unroll
        for (int q = 0; q < 4; q++) {
            float p0 = t0 * e0[q][0], p1 = t0 * e0[q][1], p2 = t0 * e0[q][2], p3 = t0 * e0[q][3];
            float s0 = t1 * e1[q][0], s1 = t1 * e1[q][1], s2 = t1 * e1[q][2], s3 = t1 * e1[q][3];
            uint32_t a0h = pack_hi2(p0, p1), a2h = pack_hi2(p2, p3);
            uint32_t a1h = pack_hi2(s0, s1), a3h = pack_hi2(s2, s3);
            uint32_t a0l = pack_rn2(p0 - trunc_bf(p0), p1 - trunc_bf(p1));
            uint32_t a2l = pack_rn2(p2 - trunc_bf(p2), p3 - trunc_bf(p3));
            uint32_t a1l = pack_rn2(s0 - trunc_bf(s0), s1 - trunc_bf(s1));
            uint32_t a3l = pack_rn2(s2 - trunc_bf(s2), s3 - trunc_bf(s3));
            int ki = (i << 2) + q;
#pragma unroll
            for (int nt = 0; nt < 8; nt++) {
                uint4 bf = __ldg(bfr + (((ki << 3) + nt) << 5));
                mma_bf16(acc[nt], a0h, a1h, a2h, a3h, bf.x, bf.y);   // hi*hi
                mma_bf16(acc[nt], a0h, a1h, a2h, a3h, bf.z, bf.w);   // hi*lo
                mma_bf16(acc[nt], a0l, a1l, a2l, a3l, bf.x, bf.y);   // lo*hi
            }
        }
    }

    float* ob = g_tmp[par ^ 1] + (size_t)sb * RR;
#pragma unroll
    for (int nt = 0; nt < 8; nt++) {
        int col = nt * 8 + 2 * tq;
        *(float2*)(ob + (size_t)r0 * RR + col) = make_float2(acc[nt][0], acc[nt][1]);
        *(float2*)(ob + (size_t)r1 * RR + col) = make_float2(acc[nt][2], acc[nt][3]);
    }
}

// ---------------------------------------------------------------- phi (128 samples/block)
__device__ __forceinline__ void lse_upd(float& M, float& S, float v) {
    float Mn = fmaxf(M, v);
    S = S * __expf(M - Mn) + __expf(v - Mn);
    M = Mn;
}

__global__ __launch_bounds__(256) void phi_kernel(int t, int par,
        const float* __restrict__ b1, const float* __restrict__ b2,
        const float* __restrict__ mub, const float* __restrict__ sgb,
        const float* __restrict__ alb, float* __restrict__ out) {
    extern __shared__ __align__(16) float ps[];
    float* sT  = ps;                 // [64][132] tmp transposed [i][s]
    float* sH1 = ps + 64 * 132;      // [64][132]
    float* sH2 = ps + 2 * 64 * 132;  // [64][132]
    __shared__ float sred[256];
    __shared__ float lred[8][32][8];
    int tid = threadIdx.x;
    int bs = blockIdx.x * 128;

    const float4* t4 = (const float4*)(g_tmp[par] + (size_t)bs * RR);
    float sq = 0.f;
    for (int v = tid; v < 2048; v += 256) {
        int s = v >> 4, c = (v & 15) << 2;
        float4 a = t4[v];
        sq += a.x * a.x + a.y * a.y + a.z * a.z + a.w * a.w;
        sT[(c + 0) * 132 + s] = a.x; sT[(c + 1) * 132 + s] = a.y;
        sT[(c + 2) * 132 + s] = a.z; sT[(c + 3) * 132 + s] = a.w;
    }
    sred[tid] = sq;
    __syncthreads();
    for (int off = 128; off > 0; off >>= 1) {
        if (tid < off) sred[tid] += sred[tid + off];
        __syncthreads();
    }
    if (tid == 0) g_npart[t * PHI_B + blockIdx.x] = sred[0];

    int et = (tid & 7) << 3;       // 8-wide output tile
    int st = (tid >> 3) << 2;      // 4-sample group
    float acc[4][8];
#pragma unroll
    for (int u = 0; u < 4; u++)
#pragma unroll
        for (int k = 0; k < 8; k++) acc[u][k] = 0.f;

    for (int c = 0; c < 8; c++) {
        float a[4][8];
#pragma unroll
        for (int u = 0; u < 4; u++)
#pragma unroll
            for (int k = 0; k < 8; k++) a[u][k] = 0.f;
#pragma unroll 8
        for (int i = 0; i < RR; i++) {
            float4 tv = *(const float4*)&sT[i * 132 + st];
            const float4* wp = (const float4*)(g_w1T + i * HN + c * 64 + et);
            float4 w0 = __ldg(wp);
            float4 w1v = __ldg(wp + 1);
            float tt[4] = {tv.x, tv.y, tv.z, tv.w};
            float ww[8] = {w0.x, w0.y, w0.z, w0.w, w1v.x, w1v.y, w1v.z, w1v.w};
#pragma unroll
            for (int u = 0; u < 4; u++)
#pragma unroll
                for (int k = 0; k < 8; k++) a[u][k] = fmaf(tt[u], ww[k], a[u][k]);
        }
        {
            const float4* bp = (const float4*)(b1 + c * 64 + et);
            float4 bb0 = __ldg(bp), bb1 = __ldg(bp + 1);
            float bb[8] = {bb0.x, bb0.y, bb0.z, bb0.w, bb1.x, bb1.y, bb1.z, bb1.w};
#pragma unroll
            for (int k = 0; k < 8; k++)
                *(float4*)&sH1[(et + k) * 132 + st] =
                    make_float4(fmaxf(a[0][k] + bb[k], 0.f), fmaxf(a[1][k] + bb[k], 0.f),
                                fmaxf(a[2][k] + bb[k], 0.f), fmaxf(a[3][k] + bb[k], 0.f));
        }
        __syncthreads();
#pragma unroll 8
        for (int e = 0; e < RR; e++) {
            float4 hv = *(const float4*)&sH1[e * 132 + st];
            const float4* wp = (const float4*)(g_w2T + (size_t)(c * 64 + e) * RR + et);
            float4 w0 = __ldg(wp);
            float4 w1v = __ldg(wp + 1);
            float hh[4] = {hv.x, hv.y, hv.z, hv.w};
            float ww[8] = {w0.x, w0.y, w0.z, w0.w, w1v.x, w1v.y, w1v.z, w1v.w};
#pragma unroll
            for (int u = 0; u < 4; u++)
#pragma unroll
                for (int k = 0; k < 8; k++) acc[u][k] = fmaf(hh[u], ww[k], acc[u][k]);
        }
        __syncthreads();
    }
    {
        const float4* bp = (const float4*)(b2 + et);
        float4 bb0 = __ldg(bp), bb1 = __ldg(bp + 1);
        float bb[8] = {bb0.x, bb0.y, bb0.z, bb0.w, bb1.x, bb1.y, bb1.z, bb1.w};
#pragma unroll
        for (int k = 0; k < 8; k++)
            *(float4*)&sH2[(et + k) * 132 + st] =
                make_float4(fmaxf(acc[0][k] + bb[k], 0.f), fmaxf(acc[1][k] + bb[k], 0.f),
                            fmaxf(acc[2][k] + bb[k], 0.f), fmaxf(acc[3][k] + bb[k], 0.f));
    }
    __syncthreads();

    int lane = tid & 31, wg = tid >> 5;
    for (int ss = 0; ss < 2; ss++) {
        int s0 = ss * 64 + (lane << 1);
        float x0[8], x1[8];
        {
            const float4* xp = (const float4*)(g_XT + ((size_t)t * NN + bs + s0) * XDIM);
            float4 xa = xp[0], xb = xp[1], xc = xp[2], xd = xp[3];
            x0[0] = xa.x; x0[1] = xa.y; x0[2] = xa.z; x0[3] = xa.w;
            x0[4] = xb.x; x0[5] = xb.y; x0[6] = xb.z; x0[7] = xb.w;
            x1[0] = xc.x; x1[1] = xc.y; x1[2] = xc.z; x1[3] = xc.w;
            x1[4] = xd.x; x1[5] = xd.y; x1[6] = xd.z; x1[7] = xd.w;
        }
        float mla0 = -3.4e38f, sla0 = 0.f, mtt0 = -3.4e38f, stt0 = 0.f;
        float mla1 = -3.4e38f, sla1 = 0.f, mtt1 = -3.4e38f, stt1 = 0.f;
#pragma unroll 1
        for (int mi = 0; mi < 4; mi++) {
            int mm = (wg << 2) + mi;
            float mu0[8], mu1[8], ls0[8], ls1[8];
            float al0 = 0.f, al1 = 0.f;
#pragma unroll
            for (int q = 0; q < 8; q++) { mu0[q] = 0.f; mu1[q] = 0.f; ls0[q] = 0.f; ls1[q] = 0.f; }
#pragma unroll 4
            for (int j = 0; j < RR; j++) {
                float2 hh = *(const float2*)&sH2[j * 132 + s0];
                const float4* row = (const float4*)(g_headT + j * HEADW);
                float4 wm0 = __ldg(row + (mm << 1));
                float4 wm1 = __ldg(row + (mm << 1) + 1);
                float4 ws0 = __ldg(row + 64 + (mm << 1));
                float4 ws1 = __ldg(row + 64 + (mm << 1) + 1);
                float wa = __ldg(g_headT + j * HEADW + 512 + mm);
                float wm[8] = {wm0.x, wm0.y, wm0.z, wm0.w, wm1.x, wm1.y, wm1.z, wm1.w};
                float ws[8] = {ws0.x, ws0.y, ws0.z, ws0.w, ws1.x, ws1.y, ws1.z, ws1.w};
#pragma unroll
                for (int q = 0; q < 8; q++) {
                    mu0[q] = fmaf(hh.x, wm[q], mu0[q]);
                    mu1[q] = fmaf(hh.y, wm[q], mu1[q]);
                    ls0[q] = fmaf(hh.x, ws[q], ls0[q]);
                    ls1[q] = fmaf(hh.y, ws[q], ls1[q]);
                }
                al0 = fmaf(hh.x, wa, al0);
                al1 = fmaf(hh.y, wa, al1);
            }
            {
                const float4* mp = (const float4*)(mub + (mm << 3));
                const float4* sp = (const float4*)(sgb + (mm << 3));
                float4 m0 = __ldg(mp), m1 = __ldg(mp + 1);
                float4 sg0 = __ldg(sp), sg1 = __ldg(sp + 1);
                float mbv[8] = {m0.x, m0.y, m0.z, m0.w, m1.x, m1.y, m1.z, m1.w};
                float sbv[8] = {sg0.x, sg0.y, sg0.z, sg0.w, sg1.x, sg1.y, sg1.z, sg1.w};
                float alB = __ldg(alb + mm);
                al0 += alB; al1 += alB;
                float clp0 = -0.5f * XDIM * LOG2PI_F;
                float clp1 = -0.5f * XDIM * LOG2PI_F;
#pragma unroll
                for (int q = 0; q < 8; q++) {
                    float lq0 = ls0[q] + sbv[q];
                    float lq1 = ls1[q] + sbv[q];
                    float z0 = (x0[q] - (mu0[q] + mbv[q])) * __expf(-lq0);
                    float z1 = (x1[q] - (mu1[q] + mbv[q])) * __expf(-lq1);
                    clp0 += -0.5f * z0 * z0 - lq0;
                    clp1 += -0.5f * z1 * z1 - lq1;
                }
                lse_upd(mla0, sla0, al0); lse_upd(mtt0, stt0, al0 + clp0);
                lse_upd(mla1, sla1, al1); lse_upd(mtt1, stt1, al1 + clp1);
            }
        }
        lred[wg][lane][0] = mla0; lred[wg][lane][1] = sla0;
        lred[wg][lane][2] = mtt0; lred[wg][lane][3] = stt0;
        lred[wg][lane][4] = mla1; lred[wg][lane][5] = sla1;
        lred[wg][lane][6] = mtt1; lred[wg][lane][7] = stt1;
        __syncthreads();
        if (tid < 64) {
            int ln = tid >> 1, hf = (tid & 1) << 2;
            float M1 = -3.4e38f, S1 = 0.f, M2 = -3.4e38f, S2 = 0.f;
#pragma unroll
            for (int k = 0; k < 8; k++) {
                float gm = lred[k][ln][hf], gs = lred[k][ln][hf + 1];
                float Mn = fmaxf(M1, gm);
                S1 = S1 * __expf(M1 - Mn) + gs * __expf(gm - Mn);
                M1 = Mn;
                gm = lred[k][ln][hf + 2]; gs = lred[k][ln][hf + 3];
                Mn = fmaxf(M2, gm);
                S2 = S2 * __expf(M2 - Mn) + gs * __expf(gm - Mn);
                M2 = Mn;
            }
            out[bs + ss * 64 + tid] += (M2 + __logf(S2)) - (M1 + __logf(S1));
        }
        __syncthreads();
    }
}

// ---------------------------------------------------------------- norm finish
__global__ void finish_kernel(float* __restrict__ out, int out_n) {
    __shared__ float red[256];
    int tid = threadIdx.x;
    float s = 0.f;
    for (int v = tid; v < LL * PHI_B; v += 256) s += g_npart[v];
    red[tid] = s;
    __syncthreads();
    for (int off = 128; off > 0; off >>= 1) {
        if (tid < off) red[tid] += red[tid + off];
        __syncthreads();
    }
    if (tid == 0) out[out_n - 1] = red[0];
}

// ---------------------------------------------------------------- launch
extern "C" void kernel_launch(void* const* d_in, const int* in_sizes, int n_in,
                              void* d_out, int out_size) {
    const float* X    = (const float*)d_in[0];
    const float* iw   = (const float*)d_in[1];
    const float* cores= (const float*)d_in[2];
    const float* e1w  = (const float*)d_in[3];
    const float* e1b  = (const float*)d_in[4];
    const float* e2w  = (const float*)d_in[5];
    const float* e2b  = (const float*)d_in[6];
    const float* nw1  = (const float*)d_in[7];
    const float* nb1  = (const float*)d_in[8];
    const float* nw2  = (const float*)d_in[9];
    const float* nb2  = (const float*)d_in[10];
    const float* muw  = (const float*)d_in[11];
    const float* mub  = (const float*)d_in[12];
    const float* sgw  = (const float*)d_in[13];
    const float* sgb  = (const float*)d_in[14];
    const float* alw  = (const float*)d_in[15];
    const float* alb  = (const float*)d_in[16];
    float* out = (float*)d_out;

    cudaFuncSetAttribute(phi_kernel, cudaFuncAttributeMaxDynamicSharedMemorySize, PHI_SMEM);

    prep_kernel<<<(RR * HEADW + 255) / 256, 256>>>(e2w, nw1, nw2, muw, sgw, alw);
    prep_bfrag_kernel<<<((LL - 1) * 256 * 8 * 32 + 255) / 256, 256>>>(cores);
    init_kernel<<<(NN * RR) / 256, 256>>>(iw, out, out_size);
    enc_kernel<<<(LL * NN) / 256, 256>>>(X, e1w, e1b, e2b);

    phi_kernel<<<PHI_B, 256, PHI_SMEM>>>(0, 0, nb1, nb2, mub, sgb, alb, out);
    for (int t = 1; t < LL; t++) {
        update_mma_kernel<<<NN / 128, 256>>>(t, (t - 1) & 1);
        phi_kernel<<<PHI_B, 256, PHI_SMEM>>>(t, t & 1, nb1, nb2, mub, sgb, alb, out);
    }
    finish_kernel<<<1, 256>>>(out, out_size);
}

// round 11
// speedup vs baseline: 6.7143x; 1.5903x over previous
#include <cuda_runtime.h>
#include <cuda_bf16.h>
#include <cstdint>
#include <math.h>

#define NN 32768
#define XDIM 8
#define LL 16
#define DD 64
#define RR 64
#define HE 256
#define HN 512
#define MX 32
#define LOG2PI_F 1.8378770664093453f
#define PHI_B (NN / 128)

// scratch (device globals: allocation-free contract)
__device__ float g_enc[(size_t)LL * NN * DD];
__device__ float g_XT[(size_t)LL * NN * XDIM];
__device__ float g_tmp[2][(size_t)NN * RR];
__device__ float g_e2T[HE * DD];
__device__ float g_npart[LL * PHI_B];
// B fragments, mma-ready: {b0hi,b1hi,b0lo,b1lo} per lane
__device__ uint4 g_Bfrag[(size_t)(LL - 1) * 256 * 8 * 32];  // update: [step][kiter256][ntile8][lane]
__device__ uint4 g_w1frag[4 * 64 * 32];                     // phi stage1: [kc4][ntile64][lane]
__device__ uint4 g_w2frag[32 * 8 * 32];                     // phi stage2: [kc32][ntile8][lane]
__device__ uint4 g_hfrag[68 * 4 * 32];                      // phi head:   [ntile68][kc4][lane]

// ---------------------------------------------------------------- helpers
__device__ __forceinline__ uint32_t pack_hi2(float lo_elem, float hi_elem) {
    return __byte_perm(__float_as_uint(lo_elem), __float_as_uint(hi_elem), 0x7632);
}
__device__ __forceinline__ uint32_t pack_rn2(float lo_elem, float hi_elem) {
    uint32_t r;
    asm("cvt.rn.bf16x2.f32 %0, %1, %2;" : "=r"(r) : "f"(hi_elem), "f"(lo_elem));
    return r;
}
__device__ __forceinline__ float trunc_bf(float v) {
    return __uint_as_float(__float_as_uint(v) & 0xFFFF0000u);
}
__device__ __forceinline__ void mma_bf16(float* c,
        uint32_t a0, uint32_t a1, uint32_t a2, uint32_t a3,
        uint32_t b0, uint32_t b1) {
    asm volatile(
        "mma.sync.aligned.m16n8k16.row.col.f32.bf16.bf16.f32 "
        "{%0,%1,%2,%3}, {%4,%5,%6,%7}, {%8,%9}, {%0,%1,%2,%3};"
        : "+f"(c[0]), "+f"(c[1]), "+f"(c[2]), "+f"(c[3])
        : "r"(a0), "r"(a1), "r"(a2), "r"(a3), "r"(b0), "r"(b1));
}
// 3-split mma: AhiBhi + AhiBlo + AloBhi
__device__ __forceinline__ void mma3(float* c, const uint32_t* ah, const uint32_t* al,
                                     const uint4& bf) {
    mma_bf16(c, ah[0], ah[1], ah[2], ah[3], bf.x, bf.y);
    mma_bf16(c, ah[0], ah[1], ah[2], ah[3], bf.z, bf.w);
    mma_bf16(c, al[0], al[1], al[2], al[3], bf.x, bf.y);
}
__device__ __forceinline__ void lse_upd(float& M, float& S, float v) {
    float Mn = fmaxf(M, v);
    S = S * __expf(M - Mn) + __expf(v - Mn);
    M = Mn;
}

// ---------------------------------------------------------------- prep
__global__ void prep_kernel(const float* __restrict__ e2w) {
    int idx = blockIdx.x * blockDim.x + threadIdx.x;
    if (idx < HE * DD) { int e = idx / DD, d = idx % DD; g_e2T[idx] = e2w[d * HE + e]; }
}

// pack a 2x2 k-group of B values into the mma fragment quad
__device__ __forceinline__ uint4 pack_bquad(float v00, float v01, float v10, float v11) {
    uint4 r;
    r.x = pack_hi2(v00, v01);
    r.y = pack_hi2(v10, v11);
    r.z = pack_rn2(v00 - trunc_bf(v00), v01 - trunc_bf(v01));
    r.w = pack_rn2(v10 - trunc_bf(v10), v11 - trunc_bf(v11));
    return r;
}

// update-kernel B fragments from cores
__global__ void prep_bfrag_kernel(const float* __restrict__ cores) {
    int idx = blockIdx.x * blockDim.x + threadIdx.x;
    if (idx >= (LL - 1) * 256 * 8 * 32) return;
    int lane = idx & 31;
    int nt = (idx >> 5) & 7;
    int ki = (idx >> 8) & 255;
    int l = idx >> 16;
    int g = lane >> 2, tq = lane & 3;
    int n = nt * 8 + g;
    int k0 = ki * 16 + 2 * tq;
    const float* base = cores + (size_t)l * 262144 + (size_t)k0 * 64 + n;
    g_Bfrag[idx] = pack_bquad(base[0], base[64], base[512], base[576]);
}

// phi-kernel weight fragments
__global__ void prep_stage_frags(const float* __restrict__ nw1, const float* __restrict__ nw2,
                                 const float* __restrict__ muw, const float* __restrict__ sgw,
                                 const float* __restrict__ alw) {
    int idx = blockIdx.x * 256 + threadIdx.x;
    if (idx < 8192) {
        int lane = idx & 31, g = lane >> 2, tq = lane & 3;
        int nt = (idx >> 5) & 63;
        int n = nt * 8 + g, k0 = ((idx >> 11) * 16) + 2 * tq;
        const float* w = nw1 + n * RR;
        g_w1frag[idx] = pack_bquad(w[k0], w[k0 + 1], w[k0 + 8], w[k0 + 9]);
    } else if (idx < 16384) {
        int j = idx - 8192;
        int lane = j & 31, g = lane >> 2, tq = lane & 3;
        int nt = (j >> 5) & 7;
        int n = nt * 8 + g, k0 = ((j >> 8) * 16) + 2 * tq;
        const float* w = nw2 + n * HN;
        g_w2frag[j] = pack_bquad(w[k0], w[k0 + 1], w[k0 + 8], w[k0 + 9]);
    } else if (idx < 16384 + 8704) {
        int j = idx - 16384;
        int lane = j & 31, g = lane >> 2, tq = lane & 3;
        int kc = (j >> 5) & 3, nt = j >> 7;
        int n = nt * 8 + g, k0 = kc * 16 + 2 * tq;
        const float* w;
        if (n < 512) {
            int m = n >> 4, inner = n & 15;
            w = (inner < 8) ? muw + (m * 8 + inner) * RR : sgw + (m * 8 + inner - 8) * RR;
        } else {
            w = alw + (n - 512) * RR;
        }
        g_hfrag[j] = pack_bquad(w[k0], w[k0 + 1], w[k0 + 8], w[k0 + 9]);
    }
}

__global__ void init_kernel(const float* __restrict__ iw, float* __restrict__ out, int out_n) {
    int idx = blockIdx.x * blockDim.x + threadIdx.x;
    if (idx < NN * RR) g_tmp[0][idx] = iw[idx & (RR - 1)];
    if (idx < out_n) out[idx] = 0.f;
}

// ---------------------------------------------------------------- encoder
__global__ __launch_bounds__(256) void enc_kernel(const float* __restrict__ X,
        const float* __restrict__ w1, const float* __restrict__ b1,
        const float* __restrict__ b2) {
    int id = blockIdx.x * 256 + threadIdx.x;
    int l = id & (LL - 1);
    int n = id >> 4;
    float x[XDIM];
#pragma unroll
    for (int k = 0; k < XDIM; k++) x[k] = X[((size_t)n * XDIM + k) * LL + l];
    float4* xt = (float4*)&g_XT[((size_t)l * NN + n) * XDIM];
    xt[0] = make_float4(x[0], x[1], x[2], x[3]);
    xt[1] = make_float4(x[4], x[5], x[6], x[7]);
    float acc[DD];
#pragma unroll
    for (int d = 0; d < DD; d++) acc[d] = 0.f;
    for (int e = 0; e < HE; e++) {
        const float4* w4 = (const float4*)&w1[e * XDIM];
        float4 wa = __ldg(&w4[0]);
        float4 wb = __ldg(&w4[1]);
        float h = __ldg(&b1[e]);
        h += wa.x * x[0] + wa.y * x[1] + wa.z * x[2] + wa.w * x[3];
        h += wb.x * x[4] + wb.y * x[5] + wb.z * x[6] + wb.w * x[7];
        h = fmaxf(h, 0.f);
        const float4* et = (const float4*)&g_e2T[e * DD];
#pragma unroll
        for (int q = 0; q < 16; q++) {
            float4 a = et[q];
            acc[4*q+0] += a.x * h; acc[4*q+1] += a.y * h;
            acc[4*q+2] += a.z * h; acc[4*q+3] += a.w * h;
        }
    }
    float4* o = (float4*)&g_enc[((size_t)l * NN + n) * DD];
#pragma unroll
    for (int q = 0; q < 16; q++) {
        o[q] = make_float4(acc[4*q+0] + __ldg(&b2[4*q+0]),
                           acc[4*q+1] + __ldg(&b2[4*q+1]),
                           acc[4*q+2] + __ldg(&b2[4*q+2]),
                           acc[4*q+3] + __ldg(&b2[4*q+3]));
    }
}

// ---------------------------------------------------------------- recurrence update (mma.sync bf16)
__global__ __launch_bounds__(256, 2) void update_mma_kernel(int t, int par) {
    __shared__ float sTmp[128][68];
    int tid = threadIdx.x;
    int wid = tid >> 5, lane = tid & 31;
    int g = lane >> 2, tq = lane & 3;
    int sb = blockIdx.x * 128;
    int r0 = wid * 16 + g, r1 = r0 + 8;

    const float4* tin4 = (const float4*)(g_tmp[par] + (size_t)sb * RR);
    for (int v = tid; v < 2048; v += 256) {
        int r = v >> 4, c = (v & 15) << 2;
        *(float4*)&sTmp[r][c] = tin4[v];
    }
    float e0[4][4], e1[4][4];
    {
        const float* ep0 = g_enc + ((size_t)(t - 1) * NN + sb + r0) * DD;
        const float* ep1 = g_enc + ((size_t)(t - 1) * NN + sb + r1) * DD;
#pragma unroll
        for (int q = 0; q < 4; q++) {
            float2 a = __ldg((const float2*)(ep0 + q * 16 + 2 * tq));
            float2 b = __ldg((const float2*)(ep0 + q * 16 + 2 * tq + 8));
            e0[q][0] = a.x; e0[q][1] = a.y; e0[q][2] = b.x; e0[q][3] = b.y;
            float2 c = __ldg((const float2*)(ep1 + q * 16 + 2 * tq));
            float2 d = __ldg((const float2*)(ep1 + q * 16 + 2 * tq + 8));
            e1[q][0] = c.x; e1[q][1] = c.y; e1[q][2] = d.x; e1[q][3] = d.y;
        }
    }
    __syncthreads();

    float acc[8][4];
#pragma unroll
    for (int nt = 0; nt < 8; nt++)
#pragma unroll
        for (int c = 0; c < 4; c++) acc[nt][c] = 0.f;

    const uint4* bfr = g_Bfrag + (size_t)(t - 1) * 65536 + lane;

    for (int i = 0; i < 64; i++) {
        float t0 = sTmp[r0][i];
        float t1 = sTmp[r1][i];
#pragma unroll
        for (int q = 0; q < 4; q++) {
            float p0 = t0 * e0[q][0], p1 = t0 * e0[q][1], p2 = t0 * e0[q][2], p3 = t0 * e0[q][3];
            float s0 = t1 * e1[q][0], s1 = t1 * e1[q][1], s2 = t1 * e1[q][2], s3 = t1 * e1[q][3];
            uint32_t a0h = pack_hi2(p0, p1), a2h = pack_hi2(p2, p3);
            uint32_t a1h = pack_hi2(s0, s1), a3h = pack_hi2(s2, s3);
            uint32_t a0l = pack_rn2(p0 - trunc_bf(p0), p1 - trunc_bf(p1));
            uint32_t a2l = pack_rn2(p2 - trunc_bf(p2), p3 - trunc_bf(p3));
            uint32_t a1l = pack_rn2(s0 - trunc_bf(s0), s1 - trunc_bf(s1));
            uint32_t a3l = pack_rn2(s2 - trunc_bf(s2), s3 - trunc_bf(s3));
            int ki = (i << 2) + q;
#pragma unroll
            for (int nt = 0; nt < 8; nt++) {
                uint4 bf = __ldg(bfr + (((ki << 3) + nt) << 5));
                mma_bf16(acc[nt], a0h, a1h, a2h, a3h, bf.x, bf.y);
                mma_bf16(acc[nt], a0h, a1h, a2h, a3h, bf.z, bf.w);
                mma_bf16(acc[nt], a0l, a1l, a2l, a3l, bf.x, bf.y);
            }
        }
    }

    float* ob = g_tmp[par ^ 1] + (size_t)sb * RR;
#pragma unroll
    for (int nt = 0; nt < 8; nt++) {
        int col = nt * 8 + 2 * tq;
        *(float2*)(ob + (size_t)r0 * RR + col) = make_float2(acc[nt][0], acc[nt][1]);
        *(float2*)(ob + (size_t)r1 * RR + col) = make_float2(acc[nt][2], acc[nt][3]);
    }
}

// ---------------------------------------------------------------- phi (full mma chain)
// block = 128 samples, 8 warps x 16 rows. Chain: tmp(64) ->relu h1(512) ->relu h2(64) -> head(544).
// C-frag(m16n8 pair) == A-frag(m16k16): activations stay in registers between layers.
__global__ __launch_bounds__(256) void phi_kernel(int t, int par,
        const float* __restrict__ b1, const float* __restrict__ b2,
        const float* __restrict__ mub, const float* __restrict__ sgb,
        const float* __restrict__ alb, float* __restrict__ out) {
    __shared__ float sT[64 * 132];   // tmp transposed [k][s]; later reused as alpha bcast [128][33]
    __shared__ float sred[256];
    int tid = threadIdx.x;
    int wid = tid >> 5, lane = tid & 31;
    int g = lane >> 2, tq = lane & 3;
    int bs = blockIdx.x * 128;
    int r0 = wid * 16 + g, r1 = r0 + 8;

    // stage tmp transposed + norm partial
    const float4* t4 = (const float4*)(g_tmp[par] + (size_t)bs * RR);
    float sq = 0.f;
    for (int v = tid; v < 2048; v += 256) {
        int s = v >> 4, c = (v & 15) << 2;
        float4 a = t4[v];
        sq += a.x * a.x + a.y * a.y + a.z * a.z + a.w * a.w;
        sT[(c + 0) * 132 + s] = a.x; sT[(c + 1) * 132 + s] = a.y;
        sT[(c + 2) * 132 + s] = a.z; sT[(c + 3) * 132 + s] = a.w;
    }
    sred[tid] = sq;
    __syncthreads();
    for (int off = 128; off > 0; off >>= 1) {
        if (tid < off) sred[tid] += sred[tid + off];
        __syncthreads();
    }
    if (tid == 0) g_npart[t * PHI_B + blockIdx.x] = sred[0];

    // A1 fragments from tmp
    uint32_t A1h[4][4], A1l[4][4];
#pragma unroll
    for (int ki = 0; ki < 4; ki++) {
        int k0 = ki * 16 + 2 * tq;
        float v00 = sT[k0 * 132 + r0],       v01 = sT[(k0 + 1) * 132 + r0];
        float v10 = sT[k0 * 132 + r1],       v11 = sT[(k0 + 1) * 132 + r1];
        float v20 = sT[(k0 + 8) * 132 + r0], v21 = sT[(k0 + 9) * 132 + r0];
        float v30 = sT[(k0 + 8) * 132 + r1], v31 = sT[(k0 + 9) * 132 + r1];
        A1h[ki][0] = pack_hi2(v00, v01); A1l[ki][0] = pack_rn2(v00 - trunc_bf(v00), v01 - trunc_bf(v01));
        A1h[ki][1] = pack_hi2(v10, v11); A1l[ki][1] = pack_rn2(v10 - trunc_bf(v10), v11 - trunc_bf(v11));
        A1h[ki][2] = pack_hi2(v20, v21); A1l[ki][2] = pack_rn2(v20 - trunc_bf(v20), v21 - trunc_bf(v21));
        A1h[ki][3] = pack_hi2(v30, v31); A1l[ki][3] = pack_rn2(v30 - trunc_bf(v30), v31 - trunc_bf(v31));
    }
    __syncthreads();   // all sT reads done -> safe to reuse as sAl later

    float acc2[8][4];
#pragma unroll
    for (int nt = 0; nt < 8; nt++)
#pragma unroll
        for (int c = 0; c < 4; c++) acc2[nt][c] = 0.f;

    // fused stage1 -> stage2, per 64-col chunk of h1
    for (int c = 0; c < 8; c++) {
        float C1[8][4];
#pragma unroll
        for (int nt2 = 0; nt2 < 8; nt2++) {
#pragma unroll
            for (int q = 0; q < 4; q++) C1[nt2][q] = 0.f;
#pragma unroll
            for (int ki = 0; ki < 4; ki++) {
                uint4 bf = __ldg(g_w1frag + (ki * 64 + c * 8 + nt2) * 32 + lane);
                mma3(C1[nt2], A1h[ki], A1l[ki], bf);
            }
        }
        uint32_t A2h[4][4], A2l[4][4];
#pragma unroll
        for (int j = 0; j < 4; j++) {
            int colA = c * 64 + j * 16 + 2 * tq;
            float ba0 = __ldg(b1 + colA), ba1 = __ldg(b1 + colA + 1);
            float bb0 = __ldg(b1 + colA + 8), bb1 = __ldg(b1 + colA + 9);
            float u00 = fmaxf(C1[2*j][0] + ba0, 0.f),   u01 = fmaxf(C1[2*j][1] + ba1, 0.f);
            float u10 = fmaxf(C1[2*j][2] + ba0, 0.f),   u11 = fmaxf(C1[2*j][3] + ba1, 0.f);
            float u20 = fmaxf(C1[2*j+1][0] + bb0, 0.f), u21 = fmaxf(C1[2*j+1][1] + bb1, 0.f);
            float u30 = fmaxf(C1[2*j+1][2] + bb0, 0.f), u31 = fmaxf(C1[2*j+1][3] + bb1, 0.f);
            A2h[j][0] = pack_hi2(u00, u01); A2l[j][0] = pack_rn2(u00 - trunc_bf(u00), u01 - trunc_bf(u01));
            A2h[j][1] = pack_hi2(u10, u11); A2l[j][1] = pack_rn2(u10 - trunc_bf(u10), u11 - trunc_bf(u11));
            A2h[j][2] = pack_hi2(u20, u21); A2l[j][2] = pack_rn2(u20 - trunc_bf(u20), u21 - trunc_bf(u21));
            A2h[j][3] = pack_hi2(u30, u31); A2l[j][3] = pack_rn2(u30 - trunc_bf(u30), u31 - trunc_bf(u31));
        }
#pragma unroll
        for (int j = 0; j < 4; j++) {
            int kc = c * 4 + j;
#pragma unroll
            for (int nt = 0; nt < 8; nt++) {
                uint4 bf = __ldg(g_w2frag + (kc * 8 + nt) * 32 + lane);
                mma3(acc2[nt], A2h[j], A2l[j], bf);
            }
        }
    }

    // h2 -> A3 fragments
    uint32_t A3h[4][4], A3l[4][4];
#pragma unroll
    for (int j = 0; j < 4; j++) {
        int colA = j * 16 + 2 * tq;
        float ba0 = __ldg(b2 + colA), ba1 = __ldg(b2 + colA + 1);
        float bb0 = __ldg(b2 + colA + 8), bb1 = __ldg(b2 + colA + 9);
        float u00 = fmaxf(acc2[2*j][0] + ba0, 0.f),   u01 = fmaxf(acc2[2*j][1] + ba1, 0.f);
        float u10 = fmaxf(acc2[2*j][2] + ba0, 0.f),   u11 = fmaxf(acc2[2*j][3] + ba1, 0.f);
        float u20 = fmaxf(acc2[2*j+1][0] + bb0, 0.f), u21 = fmaxf(acc2[2*j+1][1] + bb1, 0.f);
        float u30 = fmaxf(acc2[2*j+1][2] + bb0, 0.f), u31 = fmaxf(acc2[2*j+1][3] + bb1, 0.f);
        A3h[j][0] = pack_hi2(u00, u01); A3l[j][0] = pack_rn2(u00 - trunc_bf(u00), u01 - trunc_bf(u01));
        A3h[j][1] = pack_hi2(u10, u11); A3l[j][1] = pack_rn2(u10 - trunc_bf(u10), u11 - trunc_bf(u11));
        A3h[j][2] = pack_hi2(u20, u21); A3l[j][2] = pack_rn2(u20 - trunc_bf(u20), u21 - trunc_bf(u21));
        A3h[j][3] = pack_hi2(u30, u31); A3l[j][3] = pack_rn2(u30 - trunc_bf(u30), u31 - trunc_bf(u31));
    }

    // alpha head (ntiles 64..67)
    float alp[4][4];
#pragma unroll
    for (int nt = 0; nt < 4; nt++) {
#pragma unroll
        for (int q = 0; q < 4; q++) alp[nt][q] = 0.f;
#pragma unroll
        for (int kc = 0; kc < 4; kc++) {
            uint4 bf = __ldg(g_hfrag + ((64 + nt) * 4 + kc) * 32 + lane);
            mma3(alp[nt], A3h[kc], A3l[kc], bf);
        }
        float a0b = __ldg(alb + nt * 8 + 2 * tq), a1b = __ldg(alb + nt * 8 + 2 * tq + 1);
        alp[nt][0] += a0b; alp[nt][1] += a1b; alp[nt][2] += a0b; alp[nt][3] += a1b;
    }
    // broadcast alphas through reused smem (each warp touches only its own rows)
    float* sAl = sT;
#pragma unroll
    for (int nt = 0; nt < 4; nt++) {
        sAl[r0 * 33 + nt * 8 + 2 * tq]     = alp[nt][0];
        sAl[r0 * 33 + nt * 8 + 2 * tq + 1] = alp[nt][1];
        sAl[r1 * 33 + nt * 8 + 2 * tq]     = alp[nt][2];
        sAl[r1 * 33 + nt * 8 + 2 * tq + 1] = alp[nt][3];
    }
    __syncwarp();

    // log-softmax denominator: lse over alpha per row
    float Mg = -3.4e38f, Sg = 0.f, Mh = -3.4e38f, Sh = 0.f;
#pragma unroll
    for (int nt = 0; nt < 4; nt++) {
        lse_upd(Mg, Sg, alp[nt][0]); lse_upd(Mg, Sg, alp[nt][1]);
        lse_upd(Mh, Sh, alp[nt][2]); lse_upd(Mh, Sh, alp[nt][3]);
    }
#pragma unroll
    for (int dd = 1; dd < 4; dd <<= 1) {
        float Mo = __shfl_xor_sync(0xffffffffu, Mg, dd);
        float So = __shfl_xor_sync(0xffffffffu, Sg, dd);
        float Mn = fmaxf(Mg, Mo);
        Sg = Sg * __expf(Mg - Mn) + So * __expf(Mo - Mn); Mg = Mn;
        Mo = __shfl_xor_sync(0xffffffffu, Mh, dd);
        So = __shfl_xor_sync(0xffffffffu, Sh, dd);
        Mn = fmaxf(Mh, Mo);
        Sh = Sh * __expf(Mh - Mn) + So * __expf(Mo - Mn); Mh = Mn;
    }

    // x values for this lane's (row, q) pairs
    const float* xp = g_XT + ((size_t)t * NN + bs) * XDIM;
    float2 xa = *(const float2*)(xp + r0 * XDIM + 2 * tq);
    float2 xb = *(const float2*)(xp + r1 * XDIM + 2 * tq);

    float Mtg = -3.4e38f, Stg = 0.f, Mth = -3.4e38f, Sth = 0.f;
#pragma unroll 4
    for (int m = 0; m < 32; m++) {
        float Cm[4] = {0.f, 0.f, 0.f, 0.f}, Cs[4] = {0.f, 0.f, 0.f, 0.f};
#pragma unroll
        for (int kc = 0; kc < 4; kc++) {
            uint4 bm = __ldg(g_hfrag + ((2 * m) * 4 + kc) * 32 + lane);
            mma3(Cm, A3h[kc], A3l[kc], bm);
            uint4 bv = __ldg(g_hfrag + ((2 * m + 1) * 4 + kc) * 32 + lane);
            mma3(Cs, A3h[kc], A3l[kc], bv);
        }
        float mb0 = __ldg(mub + m * 8 + 2 * tq), mb1 = __ldg(mub + m * 8 + 2 * tq + 1);
        float sb0 = __ldg(sgb + m * 8 + 2 * tq), sb1 = __ldg(sgb + m * 8 + 2 * tq + 1);
        float l0 = Cs[0] + sb0, l1 = Cs[1] + sb1, l2 = Cs[2] + sb0, l3 = Cs[3] + sb1;
        float z0 = (xa.x - (Cm[0] + mb0)) * __expf(-l0);
        float z1 = (xa.y - (Cm[1] + mb1)) * __expf(-l1);
        float z2 = (xb.x - (Cm[2] + mb0)) * __expf(-l2);
        float z3 = (xb.y - (Cm[3] + mb1)) * __expf(-l3);
        float cg = -0.5f * z0 * z0 - l0 - 0.5f * z1 * z1 - l1;
        float ch = -0.5f * z2 * z2 - l2 - 0.5f * z3 * z3 - l3;
        cg += __shfl_xor_sync(0xffffffffu, cg, 1);
        cg += __shfl_xor_sync(0xffffffffu, cg, 2);
        ch += __shfl_xor_sync(0xffffffffu, ch, 1);
        ch += __shfl_xor_sync(0xffffffffu, ch, 2);
        cg += -0.5f * XDIM * LOG2PI_F;
        ch += -0.5f * XDIM * LOG2PI_F;
        float ag = sAl[r0 * 33 + m], ah = sAl[r1 * 33 + m];
        lse_upd(Mtg, Stg, ag + cg);
        lse_upd(Mth, Sth, ah + ch);
    }
    if (tq == 0) {
        out[bs + r0] += (Mtg + __logf(Stg)) - (Mg + __logf(Sg));
        out[bs + r1] += (Mth + __logf(Sth)) - (Mh + __logf(Sh));
    }
}

// ---------------------------------------------------------------- norm finish
__global__ void finish_kernel(float* __restrict__ out, int out_n) {
    __shared__ float red[256];
    int tid = threadIdx.x;
    float s = 0.f;
    for (int v = tid; v < LL * PHI_B; v += 256) s += g_npart[v];
    red[tid] = s;
    __syncthreads();
    for (int off = 128; off > 0; off >>= 1) {
        if (tid < off) red[tid] += red[tid + off];
        __syncthreads();
    }
    if (tid == 0) out[out_n - 1] = red[0];
}

// ---------------------------------------------------------------- launch
extern "C" void kernel_launch(void* const* d_in, const int* in_sizes, int n_in,
                              void* d_out, int out_size) {
    const float* X    = (const float*)d_in[0];
    const float* iw   = (const float*)d_in[1];
    const float* cores= (const float*)d_in[2];
    const float* e1w  = (const float*)d_in[3];
    const float* e1b  = (const float*)d_in[4];
    const float* e2w  = (const float*)d_in[5];
    const float* e2b  = (const float*)d_in[6];
    const float* nw1  = (const float*)d_in[7];
    const float* nb1  = (const float*)d_in[8];
    const float* nw2  = (const float*)d_in[9];
    const float* nb2  = (const float*)d_in[10];
    const float* muw  = (const float*)d_in[11];
    const float* mub  = (const float*)d_in[12];
    const float* sgw  = (const float*)d_in[13];
    const float* sgb  = (const float*)d_in[14];
    const float* alw  = (const float*)d_in[15];
    const float* alb  = (const float*)d_in[16];
    float* out = (float*)d_out;

    prep_kernel<<<(HE * DD + 255) / 256, 256>>>(e2w);
    prep_bfrag_kernel<<<((LL - 1) * 256 * 8 * 32 + 255) / 256, 256>>>(cores);
    prep_stage_frags<<<(16384 + 8704 + 255) / 256, 256>>>(nw1, nw2, muw, sgw, alw);
    init_kernel<<<(NN * RR) / 256, 256>>>(iw, out, out_size);
    enc_kernel<<<(LL * NN) / 256, 256>>>(X, e1w, e1b, e2b);

    phi_kernel<<<PHI_B, 256>>>(0, 0, nb1, nb2, mub, sgb, alb, out);
    for (int t = 1; t < LL; t++) {
        update_mma_kernel<<<NN / 128, 256>>>(t, (t - 1) & 1);
        phi_kernel<<<PHI_B, 256>>>(t, t & 1, nb1, nb2, mub, sgb, alb, out);
    }
    finish_kernel<<<1, 256>>>(out, out_size);
}

// round 12
// speedup vs baseline: 7.4434x; 1.1086x over previous
#include <cuda_runtime.h>
#include <cuda_bf16.h>
#include <cstdint>
#include <math.h>

#define NN 32768
#define XDIM 8
#define LL 16
#define DD 64
#define RR 64
#define HE 256
#define HN 512
#define MX 32
#define LOG2PI_F 1.8378770664093453f
#define PHI_B (NN / 128)

// scratch (device globals: allocation-free contract)
__device__ float g_enc[(size_t)LL * NN * DD];
__device__ float g_XT[(size_t)LL * NN * XDIM];
__device__ float g_tmpAll[LL][(size_t)NN * RR];   // all recurrent states
__device__ float g_res[LL][NN];                   // per-step phi results
__device__ float g_e2T[HE * DD];
__device__ float g_npart[LL * PHI_B];
// update B fragments (3-split): {b0hi,b1hi,b0lo,b1lo} per lane
__device__ uint4 g_Bfrag[(size_t)(LL - 1) * 256 * 8 * 32];  // [step][kiter256][ntile8][lane]
// phi weight fragments (plain rn bf16): {b0,b1} per lane
__device__ uint2 g_w1f[4 * 64 * 32];   // stage1: [kc4][ntile64][lane]
__device__ uint2 g_w2f[32 * 8 * 32];   // stage2: [kc32][ntile8][lane]
__device__ uint2 g_hf[68 * 4 * 32];    // head:   [ntile68][kc4][lane]

// ---------------------------------------------------------------- helpers
__device__ __forceinline__ uint32_t pack_hi2(float lo_elem, float hi_elem) {
    return __byte_perm(__float_as_uint(lo_elem), __float_as_uint(hi_elem), 0x7632);
}
__device__ __forceinline__ uint32_t pack_rn2(float lo_elem, float hi_elem) {
    uint32_t r;
    asm("cvt.rn.bf16x2.f32 %0, %1, %2;" : "=r"(r) : "f"(hi_elem), "f"(lo_elem));
    return r;
}
__device__ __forceinline__ float trunc_bf(float v) {
    return __uint_as_float(__float_as_uint(v) & 0xFFFF0000u);
}
__device__ __forceinline__ void mma_bf16(float* c,
        uint32_t a0, uint32_t a1, uint32_t a2, uint32_t a3,
        uint32_t b0, uint32_t b1) {
    asm volatile(
        "mma.sync.aligned.m16n8k16.row.col.f32.bf16.bf16.f32 "
        "{%0,%1,%2,%3}, {%4,%5,%6,%7}, {%8,%9}, {%0,%1,%2,%3};"
        : "+f"(c[0]), "+f"(c[1]), "+f"(c[2]), "+f"(c[3])
        : "r"(a0), "r"(a1), "r"(a2), "r"(a3), "r"(b0), "r"(b1));
}
__device__ __forceinline__ void mma1(float* c, const uint32_t* a, const uint2& bf) {
    mma_bf16(c, a[0], a[1], a[2], a[3], bf.x, bf.y);
}
__device__ __forceinline__ void lse_upd(float& M, float& S, float v) {
    float Mn = fmaxf(M, v);
    S = S * __expf(M - Mn) + __expf(v - Mn);
    M = Mn;
}

// ---------------------------------------------------------------- prep
__global__ void prep_kernel(const float* __restrict__ e2w) {
    int idx = blockIdx.x * blockDim.x + threadIdx.x;
    if (idx < HE * DD) { int e = idx / DD, d = idx % DD; g_e2T[idx] = e2w[d * HE + e]; }
}

__device__ __forceinline__ uint4 pack_bquad(float v00, float v01, float v10, float v11) {
    uint4 r;
    r.x = pack_hi2(v00, v01);
    r.y = pack_hi2(v10, v11);
    r.z = pack_rn2(v00 - trunc_bf(v00), v01 - trunc_bf(v01));
    r.w = pack_rn2(v10 - trunc_bf(v10), v11 - trunc_bf(v11));
    return r;
}

__global__ void prep_bfrag_kernel(const float* __restrict__ cores) {
    int idx = blockIdx.x * blockDim.x + threadIdx.x;
    if (idx >= (LL - 1) * 256 * 8 * 32) return;
    int lane = idx & 31;
    int nt = (idx >> 5) & 7;
    int ki = (idx >> 8) & 255;
    int l = idx >> 16;
    int g = lane >> 2, tq = lane & 3;
    int n = nt * 8 + g;
    int k0 = ki * 16 + 2 * tq;
    const float* base = cores + (size_t)l * 262144 + (size_t)k0 * 64 + n;
    g_Bfrag[idx] = pack_bquad(base[0], base[64], base[512], base[576]);
}

// phi weight fragments: plain rn bf16
__global__ void prep_stage_frags(const float* __restrict__ nw1, const float* __restrict__ nw2,
                                 const float* __restrict__ muw, const float* __restrict__ sgw,
                                 const float* __restrict__ alw) {
    int idx = blockIdx.x * 256 + threadIdx.x;
    if (idx < 8192) {
        int lane = idx & 31, g = lane >> 2, tq = lane & 3;
        int nt = (idx >> 5) & 63;
        int n = nt * 8 + g, k0 = ((idx >> 11) * 16) + 2 * tq;
        const float* w = nw1 + n * RR;
        g_w1f[idx] = make_uint2(pack_rn2(w[k0], w[k0 + 1]), pack_rn2(w[k0 + 8], w[k0 + 9]));
    } else if (idx < 16384) {
        int j = idx - 8192;
        int lane = j & 31, g = lane >> 2, tq = lane & 3;
        int nt = (j >> 5) & 7;
        int n = nt * 8 + g, k0 = ((j >> 8) * 16) + 2 * tq;
        const float* w = nw2 + n * HN;
        g_w2f[j] = make_uint2(pack_rn2(w[k0], w[k0 + 1]), pack_rn2(w[k0 + 8], w[k0 + 9]));
    } else if (idx < 16384 + 8704) {
        int j = idx - 16384;
        int lane = j & 31, g = lane >> 2, tq = lane & 3;
        int kc = (j >> 5) & 3, nt = j >> 7;
        int n = nt * 8 + g, k0 = kc * 16 + 2 * tq;
        const float* w;
        if (n < 512) {
            int m = n >> 4, inner = n & 15;
            w = (inner < 8) ? muw + (m * 8 + inner) * RR : sgw + (m * 8 + inner - 8) * RR;
        } else {
            w = alw + (n - 512) * RR;
        }
        g_hf[j] = make_uint2(pack_rn2(w[k0], w[k0 + 1]), pack_rn2(w[k0 + 8], w[k0 + 9]));
    }
}

__global__ void init_kernel(const float* __restrict__ iw) {
    int idx = blockIdx.x * blockDim.x + threadIdx.x;
    if (idx < NN * RR) g_tmpAll[0][idx] = iw[idx & (RR - 1)];
}

// ---------------------------------------------------------------- encoder
__global__ __launch_bounds__(256) void enc_kernel(const float* __restrict__ X,
        const float* __restrict__ w1, const float* __restrict__ b1,
        const float* __restrict__ b2) {
    int id = blockIdx.x * 256 + threadIdx.x;
    int l = id & (LL - 1);
    int n = id >> 4;
    float x[XDIM];
#pragma unroll
    for (int k = 0; k < XDIM; k++) x[k] = X[((size_t)n * XDIM + k) * LL + l];
    float4* xt = (float4*)&g_XT[((size_t)l * NN + n) * XDIM];
    xt[0] = make_float4(x[0], x[1], x[2], x[3]);
    xt[1] = make_float4(x[4], x[5], x[6], x[7]);
    float acc[DD];
#pragma unroll
    for (int d = 0; d < DD; d++) acc[d] = 0.f;
    for (int e = 0; e < HE; e++) {
        const float4* w4 = (const float4*)&w1[e * XDIM];
        float4 wa = __ldg(&w4[0]);
        float4 wb = __ldg(&w4[1]);
        float h = __ldg(&b1[e]);
        h += wa.x * x[0] + wa.y * x[1] + wa.z * x[2] + wa.w * x[3];
        h += wb.x * x[4] + wb.y * x[5] + wb.z * x[6] + wb.w * x[7];
        h = fmaxf(h, 0.f);
        const float4* et = (const float4*)&g_e2T[e * DD];
#pragma unroll
        for (int q = 0; q < 16; q++) {
            float4 a = et[q];
            acc[4*q+0] += a.x * h; acc[4*q+1] += a.y * h;
            acc[4*q+2] += a.z * h; acc[4*q+3] += a.w * h;
        }
    }
    float4* o = (float4*)&g_enc[((size_t)l * NN + n) * DD];
#pragma unroll
    for (int q = 0; q < 16; q++) {
        o[q] = make_float4(acc[4*q+0] + __ldg(&b2[4*q+0]),
                           acc[4*q+1] + __ldg(&b2[4*q+1]),
                           acc[4*q+2] + __ldg(&b2[4*q+2]),
                           acc[4*q+3] + __ldg(&b2[4*q+3]));
    }
}

// ---------------------------------------------------------------- recurrence update (mma.sync bf16, 3-split)
__global__ __launch_bounds__(256, 2) void update_mma_kernel(int t) {
    __shared__ float sTmp[128][68];
    int tid = threadIdx.x;
    int wid = tid >> 5, lane = tid & 31;
    int g = lane >> 2, tq = lane & 3;
    int sb = blockIdx.x * 128;
    int r0 = wid * 16 + g, r1 = r0 + 8;

    const float4* tin4 = (const float4*)(g_tmpAll[t - 1] + (size_t)sb * RR);
    for (int v = tid; v < 2048; v += 256) {
        int r = v >> 4, c = (v & 15) << 2;
        *(float4*)&sTmp[r][c] = tin4[v];
    }
    float e0[4][4], e1[4][4];
    {
        const float* ep0 = g_enc + ((size_t)(t - 1) * NN + sb + r0) * DD;
        const float* ep1 = g_enc + ((size_t)(t - 1) * NN + sb + r1) * DD;
#pragma unroll
        for (int q = 0; q < 4; q++) {
            float2 a = __ldg((const float2*)(ep0 + q * 16 + 2 * tq));
            float2 b = __ldg((const float2*)(ep0 + q * 16 + 2 * tq + 8));
            e0[q][0] = a.x; e0[q][1] = a.y; e0[q][2] = b.x; e0[q][3] = b.y;
            float2 c = __ldg((const float2*)(ep1 + q * 16 + 2 * tq));
            float2 d = __ldg((const float2*)(ep1 + q * 16 + 2 * tq + 8));
            e1[q][0] = c.x; e1[q][1] = c.y; e1[q][2] = d.x; e1[q][3] = d.y;
        }
    }
    __syncthreads();

    float acc[8][4];
#pragma unroll
    for (int nt = 0; nt < 8; nt++)
#pragma unroll
        for (int c = 0; c < 4; c++) acc[nt][c] = 0.f;

    const uint4* bfr = g_Bfrag + (size_t)(t - 1) * 65536 + lane;

    for (int i = 0; i < 64; i++) {
        float t0 = sTmp[r0][i];
        float t1 = sTmp[r1][i];
#pragma unroll
        for (int q = 0; q < 4; q++) {
            float p0 = t0 * e0[q][0], p1 = t0 * e0[q][1], p2 = t0 * e0[q][2], p3 = t0 * e0[q][3];
            float s0 = t1 * e1[q][0], s1 = t1 * e1[q][1], s2 = t1 * e1[q][2], s3 = t1 * e1[q][3];
            uint32_t a0h = pack_hi2(p0, p1), a2h = pack_hi2(p2, p3);
            uint32_t a1h = pack_hi2(s0, s1), a3h = pack_hi2(s2, s3);
            uint32_t a0l = pack_rn2(p0 - trunc_bf(p0), p1 - trunc_bf(p1));
            uint32_t a2l = pack_rn2(p2 - trunc_bf(p2), p3 - trunc_bf(p3));
            uint32_t a1l = pack_rn2(s0 - trunc_bf(s0), s1 - trunc_bf(s1));
            uint32_t a3l = pack_rn2(s2 - trunc_bf(s2), s3 - trunc_bf(s3));
            int ki = (i << 2) + q;
#pragma unroll
            for (int nt = 0; nt < 8; nt++) {
                uint4 bf = __ldg(bfr + (((ki << 3) + nt) << 5));
                mma_bf16(acc[nt], a0h, a1h, a2h, a3h, bf.x, bf.y);
                mma_bf16(acc[nt], a0h, a1h, a2h, a3h, bf.z, bf.w);
                mma_bf16(acc[nt], a0l, a1l, a2l, a3l, bf.x, bf.y);
            }
        }
    }

    float* ob = g_tmpAll[t] + (size_t)sb * RR;
#pragma unroll
    for (int nt = 0; nt < 8; nt++) {
        int col = nt * 8 + 2 * tq;
        *(float2*)(ob + (size_t)r0 * RR + col) = make_float2(acc[nt][0], acc[nt][1]);
        *(float2*)(ob + (size_t)r1 * RR + col) = make_float2(acc[nt][2], acc[nt][3]);
    }
}

// ---------------------------------------------------------------- phi (all 16 steps in one launch)
// grid = (PHI_B, LL). Plain rn-bf16 single-mma chain (errors don't compound; magnitudes bias-dominated).
__global__ __launch_bounds__(256) void phi_kernel(
        const float* __restrict__ b1, const float* __restrict__ b2,
        const float* __restrict__ mub, const float* __restrict__ sgb,
        const float* __restrict__ alb) {
    __shared__ float sT[64 * 132];   // tmp transposed; later reused as alpha bcast [128][33]
    __shared__ float sred[256];
    int tid = threadIdx.x;
    int wid = tid >> 5, lane = tid & 31;
    int g = lane >> 2, tq = lane & 3;
    int t = blockIdx.y;
    int bs = blockIdx.x * 128;
    int r0 = wid * 16 + g, r1 = r0 + 8;

    const float4* t4 = (const float4*)(g_tmpAll[t] + (size_t)bs * RR);
    float sq = 0.f;
    for (int v = tid; v < 2048; v += 256) {
        int s = v >> 4, c = (v & 15) << 2;
        float4 a = t4[v];
        sq += a.x * a.x + a.y * a.y + a.z * a.z + a.w * a.w;
        sT[(c + 0) * 132 + s] = a.x; sT[(c + 1) * 132 + s] = a.y;
        sT[(c + 2) * 132 + s] = a.z; sT[(c + 3) * 132 + s] = a.w;
    }
    sred[tid] = sq;
    __syncthreads();
    for (int off = 128; off > 0; off >>= 1) {
        if (tid < off) sred[tid] += sred[tid + off];
        __syncthreads();
    }
    if (tid == 0) g_npart[t * PHI_B + blockIdx.x] = sred[0];

    // A1 fragments (rn bf16)
    uint32_t A1[4][4];
#pragma unroll
    for (int ki = 0; ki < 4; ki++) {
        int k0 = ki * 16 + 2 * tq;
        A1[ki][0] = pack_rn2(sT[k0 * 132 + r0], sT[(k0 + 1) * 132 + r0]);
        A1[ki][1] = pack_rn2(sT[k0 * 132 + r1], sT[(k0 + 1) * 132 + r1]);
        A1[ki][2] = pack_rn2(sT[(k0 + 8) * 132 + r0], sT[(k0 + 9) * 132 + r0]);
        A1[ki][3] = pack_rn2(sT[(k0 + 8) * 132 + r1], sT[(k0 + 9) * 132 + r1]);
    }
    __syncthreads();   // sT reads done -> safe to reuse

    float acc2[8][4];
#pragma unroll
    for (int nt = 0; nt < 8; nt++)
#pragma unroll
        for (int c = 0; c < 4; c++) acc2[nt][c] = 0.f;

    for (int c = 0; c < 8; c++) {
        float C1[8][4];
#pragma unroll
        for (int nt2 = 0; nt2 < 8; nt2++) {
#pragma unroll
            for (int q = 0; q < 4; q++) C1[nt2][q] = 0.f;
#pragma unroll
            for (int ki = 0; ki < 4; ki++) {
                uint2 bf = __ldg(g_w1f + (ki * 64 + c * 8 + nt2) * 32 + lane);
                mma1(C1[nt2], A1[ki], bf);
            }
        }
        uint32_t A2[4][4];
#pragma unroll
        for (int j = 0; j < 4; j++) {
            int colA = c * 64 + j * 16 + 2 * tq;
            float ba0 = __ldg(b1 + colA), ba1 = __ldg(b1 + colA + 1);
            float bb0 = __ldg(b1 + colA + 8), bb1 = __ldg(b1 + colA + 9);
            A2[j][0] = pack_rn2(fmaxf(C1[2*j][0] + ba0, 0.f),   fmaxf(C1[2*j][1] + ba1, 0.f));
            A2[j][1] = pack_rn2(fmaxf(C1[2*j][2] + ba0, 0.f),   fmaxf(C1[2*j][3] + ba1, 0.f));
            A2[j][2] = pack_rn2(fmaxf(C1[2*j+1][0] + bb0, 0.f), fmaxf(C1[2*j+1][1] + bb1, 0.f));
            A2[j][3] = pack_rn2(fmaxf(C1[2*j+1][2] + bb0, 0.f), fmaxf(C1[2*j+1][3] + bb1, 0.f));
        }
#pragma unroll
        for (int j = 0; j < 4; j++) {
            int kc = c * 4 + j;
#pragma unroll
            for (int nt = 0; nt < 8; nt++) {
                uint2 bf = __ldg(g_w2f + (kc * 8 + nt) * 32 + lane);
                mma1(acc2[nt], A2[j], bf);
            }
        }
    }

    // h2 -> A3 fragments
    uint32_t A3[4][4];
#pragma unroll
    for (int j = 0; j < 4; j++) {
        int colA = j * 16 + 2 * tq;
        float ba0 = __ldg(b2 + colA), ba1 = __ldg(b2 + colA + 1);
        float bb0 = __ldg(b2 + colA + 8), bb1 = __ldg(b2 + colA + 9);
        A3[j][0] = pack_rn2(fmaxf(acc2[2*j][0] + ba0, 0.f),   fmaxf(acc2[2*j][1] + ba1, 0.f));
        A3[j][1] = pack_rn2(fmaxf(acc2[2*j][2] + ba0, 0.f),   fmaxf(acc2[2*j][3] + ba1, 0.f));
        A3[j][2] = pack_rn2(fmaxf(acc2[2*j+1][0] + bb0, 0.f), fmaxf(acc2[2*j+1][1] + bb1, 0.f));
        A3[j][3] = pack_rn2(fmaxf(acc2[2*j+1][2] + bb0, 0.f), fmaxf(acc2[2*j+1][3] + bb1, 0.f));
    }

    // alpha head (ntiles 64..67)
    float alp[4][4];
#pragma unroll
    for (int nt = 0; nt < 4; nt++) {
#pragma unroll
        for (int q = 0; q < 4; q++) alp[nt][q] = 0.f;
#pragma unroll
        for (int kc = 0; kc < 4; kc++) {
            uint2 bf = __ldg(g_hf + ((64 + nt) * 4 + kc) * 32 + lane);
            mma1(alp[nt], A3[kc], bf);
        }
        float a0b = __ldg(alb + nt * 8 + 2 * tq), a1b = __ldg(alb + nt * 8 + 2 * tq + 1);
        alp[nt][0] += a0b; alp[nt][1] += a1b; alp[nt][2] += a0b; alp[nt][3] += a1b;
    }
    float* sAl = sT;
#pragma unroll
    for (int nt = 0; nt < 4; nt++) {
        sAl[r0 * 33 + nt * 8 + 2 * tq]     = alp[nt][0];
        sAl[r0 * 33 + nt * 8 + 2 * tq + 1] = alp[nt][1];
        sAl[r1 * 33 + nt * 8 + 2 * tq]     = alp[nt][2];
        sAl[r1 * 33 + nt * 8 + 2 * tq + 1] = alp[nt][3];
    }
    __syncwarp();

    float Mg = -3.4e38f, Sg = 0.f, Mh = -3.4e38f, Sh = 0.f;
#pragma unroll
    for (int nt = 0; nt < 4; nt++) {
        lse_upd(Mg, Sg, alp[nt][0]); lse_upd(Mg, Sg, alp[nt][1]);
        lse_upd(Mh, Sh, alp[nt][2]); lse_upd(Mh, Sh, alp[nt][3]);
    }
#pragma unroll
    for (int dd = 1; dd < 4; dd <<= 1) {
        float Mo = __shfl_xor_sync(0xffffffffu, Mg, dd);
        float So = __shfl_xor_sync(0xffffffffu, Sg, dd);
        float Mn = fmaxf(Mg, Mo);
        Sg = Sg * __expf(Mg - Mn) + So * __expf(Mo - Mn); Mg = Mn;
        Mo = __shfl_xor_sync(0xffffffffu, Mh, dd);
        So = __shfl_xor_sync(0xffffffffu, Sh, dd);
        Mn = fmaxf(Mh, Mo);
        Sh = Sh * __expf(Mh - Mn) + So * __expf(Mo - Mn); Mh = Mn;
    }

    const float* xp = g_XT + ((size_t)t * NN + bs) * XDIM;
    float2 xa = *(const float2*)(xp + r0 * XDIM + 2 * tq);
    float2 xb = *(const float2*)(xp + r1 * XDIM + 2 * tq);

    float Mtg = -3.4e38f, Stg = 0.f, Mth = -3.4e38f, Sth = 0.f;
#pragma unroll 4
    for (int m = 0; m < 32; m++) {
        float Cm[4] = {0.f, 0.f, 0.f, 0.f}, Cs[4] = {0.f, 0.f, 0.f, 0.f};
#pragma unroll
        for (int kc = 0; kc < 4; kc++) {
            uint2 bm = __ldg(g_hf + ((2 * m) * 4 + kc) * 32 + lane);
            mma1(Cm, A3[kc], bm);
            uint2 bv = __ldg(g_hf + ((2 * m + 1) * 4 + kc) * 32 + lane);
            mma1(Cs, A3[kc], bv);
        }
        float mb0 = __ldg(mub + m * 8 + 2 * tq), mb1 = __ldg(mub + m * 8 + 2 * tq + 1);
        float sb0 = __ldg(sgb + m * 8 + 2 * tq), sb1 = __ldg(sgb + m * 8 + 2 * tq + 1);
        float l0 = Cs[0] + sb0, l1 = Cs[1] + sb1, l2 = Cs[2] + sb0, l3 = Cs[3] + sb1;
        float z0 = (xa.x - (Cm[0] + mb0)) * __expf(-l0);
        float z1 = (xa.y - (Cm[1] + mb1)) * __expf(-l1);
        float z2 = (xb.x - (Cm[2] + mb0)) * __expf(-l2);
        float z3 = (xb.y - (Cm[3] + mb1)) * __expf(-l3);
        float cg = -0.5f * z0 * z0 - l0 - 0.5f * z1 * z1 - l1;
        float ch = -0.5f * z2 * z2 - l2 - 0.5f * z3 * z3 - l3;
        cg += __shfl_xor_sync(0xffffffffu, cg, 1);
        cg += __shfl_xor_sync(0xffffffffu, cg, 2);
        ch += __shfl_xor_sync(0xffffffffu, ch, 1);
        ch += __shfl_xor_sync(0xffffffffu, ch, 2);
        cg += -0.5f * XDIM * LOG2PI_F;
        ch += -0.5f * XDIM * LOG2PI_F;
        float ag = sAl[r0 * 33 + m], ah = sAl[r1 * 33 + m];
        lse_upd(Mtg, Stg, ag + cg);
        lse_upd(Mth, Sth, ah + ch);
    }
    if (tq == 0) {
        g_res[t][bs + r0] = (Mtg + __logf(Stg)) - (Mg + __logf(Sg));
        g_res[t][bs + r1] = (Mth + __logf(Sth)) - (Mh + __logf(Sh));
    }
}

// ---------------------------------------------------------------- finish
__global__ void finish_kernel(float* __restrict__ out, int out_n) {
    int idx = blockIdx.x * 256 + threadIdx.x;
    if (idx < NN) {
        float s = 0.f;
#pragma unroll
        for (int t = 0; t < LL; t++) s += g_res[t][idx];
        out[idx] = s;
    } else if (idx < out_n) {
        out[idx] = 0.f;   // norm slot overwritten by norm_kernel
    }
}

__global__ void norm_kernel(float* __restrict__ out, int out_n) {
    __shared__ float red[256];
    int tid = threadIdx.x;
    float s = 0.f;
    for (int v = tid; v < LL * PHI_B; v += 256) s += g_npart[v];
    red[tid] = s;
    __syncthreads();
    for (int off = 128; off > 0; off >>= 1) {
        if (tid < off) red[tid] += red[tid + off];
        __syncthreads();
    }
    if (tid == 0) out[out_n - 1] = red[0];
}

// ---------------------------------------------------------------- launch
extern "C" void kernel_launch(void* const* d_in, const int* in_sizes, int n_in,
                              void* d_out, int out_size) {
    const float* X    = (const float*)d_in[0];
    const float* iw   = (const float*)d_in[1];
    const float* cores= (const float*)d_in[2];
    const float* e1w  = (const float*)d_in[3];
    const float* e1b  = (const float*)d_in[4];
    const float* e2w  = (const float*)d_in[5];
    const float* e2b  = (const float*)d_in[6];
    const float* nw1  = (const float*)d_in[7];
    const float* nb1  = (const float*)d_in[8];
    const float* nw2  = (const float*)d_in[9];
    const float* nb2  = (const float*)d_in[10];
    const float* muw  = (const float*)d_in[11];
    const float* mub  = (const float*)d_in[12];
    const float* sgw  = (const float*)d_in[13];
    const float* sgb  = (const float*)d_in[14];
    const float* alw  = (const float*)d_in[15];
    const float* alb  = (const float*)d_in[16];
    float* out = (float*)d_out;

    prep_kernel<<<(HE * DD + 255) / 256, 256>>>(e2w);
    prep_bfrag_kernel<<<((LL - 1) * 256 * 8 * 32 + 255) / 256, 256>>>(cores);
    prep_stage_frags<<<(16384 + 8704 + 255) / 256, 256>>>(nw1, nw2, muw, sgw, alw);
    init_kernel<<<(NN * RR + 255) / 256, 256>>>(iw);
    enc_kernel<<<(LL * NN) / 256, 256>>>(X, e1w, e1b, e2b);

    for (int t = 1; t < LL; t++)
        update_mma_kernel<<<NN / 128, 256>>>(t);

    dim3 pg(PHI_B, LL);
    phi_kernel<<<pg, 256>>>(nb1, nb2, mub, sgb, alb);

    finish_kernel<<<(out_size + 255) / 256, 256>>>(out, out_size);
    norm_kernel<<<1, 256>>>(out, out_size);
}

// round 13
// speedup vs baseline: 16.3744x; 2.1999x over previous
#include <cuda_runtime.h>
#include <cuda_bf16.h>
#include <cstdint>
#include <math.h>

#define NN 32768
#define XDIM 8
#define LL 16
#define DD 64
#define RR 64
#define HE 256
#define HN 512
#define MX 32
#define LOG2PI_F 1.8378770664093453f
#define PHI_B (NN / 128)

// scratch (device globals: allocation-free contract)
__device__ float g_enc[(size_t)LL * NN * DD];
__device__ float g_XT[(size_t)LL * NN * XDIM];
__device__ float g_tmpAll[LL][(size_t)NN * RR];   // all recurrent states
__device__ float g_res[LL][NN];                   // per-step phi results
__device__ float g_npart[LL * PHI_B];
// update B fragments (plain rn bf16): {b0,b1} per lane
__device__ uint2 g_Bf2[(size_t)(LL - 1) * 256 * 8 * 32];  // [step][kiter256][ntile8][lane]
// phi weight fragments: {b0,b1} per lane
__device__ uint2 g_w1f[4 * 64 * 32];   // stage1: [kc4][ntile64][lane]
__device__ uint2 g_w2f[32 * 8 * 32];   // stage2: [kc32][ntile8][lane]
__device__ uint2 g_hf[68 * 4 * 32];    // head:   [ntile68][kc4][lane]
// encoder weight fragments
__device__ uint32_t g_e1f[32 * 32];    // layer1 (k8): [ntile32][lane]
__device__ uint2 g_e2f[16 * 8 * 32];   // layer2 (k16): [kc16][ntile8][lane]

// ---------------------------------------------------------------- helpers
__device__ __forceinline__ uint32_t pack_rn2(float lo_elem, float hi_elem) {
    uint32_t r;
    asm("cvt.rn.bf16x2.f32 %0, %1, %2;" : "=r"(r) : "f"(hi_elem), "f"(lo_elem));
    return r;
}
__device__ __forceinline__ void mma_bf16(float* c,
        uint32_t a0, uint32_t a1, uint32_t a2, uint32_t a3,
        uint32_t b0, uint32_t b1) {
    asm volatile(
        "mma.sync.aligned.m16n8k16.row.col.f32.bf16.bf16.f32 "
        "{%0,%1,%2,%3}, {%4,%5,%6,%7}, {%8,%9}, {%0,%1,%2,%3};"
        : "+f"(c[0]), "+f"(c[1]), "+f"(c[2]), "+f"(c[3])
        : "r"(a0), "r"(a1), "r"(a2), "r"(a3), "r"(b0), "r"(b1));
}
__device__ __forceinline__ void mma_bf16_k8(float* c, uint32_t a0, uint32_t a1, uint32_t b0) {
    asm volatile(
        "mma.sync.aligned.m16n8k8.row.col.f32.bf16.bf16.f32 "
        "{%0,%1,%2,%3}, {%4,%5}, {%6}, {%0,%1,%2,%3};"
        : "+f"(c[0]), "+f"(c[1]), "+f"(c[2]), "+f"(c[3])
        : "r"(a0), "r"(a1), "r"(b0));
}
__device__ __forceinline__ void mma1(float* c, const uint32_t* a, const uint2& bf) {
    mma_bf16(c, a[0], a[1], a[2], a[3], bf.x, bf.y);
}
__device__ __forceinline__ void lse_upd(float& M, float& S, float v) {
    float Mn = fmaxf(M, v);
    S = S * __expf(M - Mn) + __expf(v - Mn);
    M = Mn;
}

// ---------------------------------------------------------------- prep
__global__ void prep_bfrag_kernel(const float* __restrict__ cores) {
    int idx = blockIdx.x * blockDim.x + threadIdx.x;
    if (idx >= (LL - 1) * 256 * 8 * 32) return;
    int lane = idx & 31;
    int nt = (idx >> 5) & 7;
    int ki = (idx >> 8) & 255;
    int l = idx >> 16;
    int g = lane >> 2, tq = lane & 3;
    int n = nt * 8 + g;
    int k0 = ki * 16 + 2 * tq;
    const float* base = cores + (size_t)l * 262144 + (size_t)k0 * 64 + n;
    g_Bf2[idx] = make_uint2(pack_rn2(base[0], base[64]), pack_rn2(base[512], base[576]));
}

__global__ void prep_stage_frags(const float* __restrict__ nw1, const float* __restrict__ nw2,
                                 const float* __restrict__ muw, const float* __restrict__ sgw,
                                 const float* __restrict__ alw,
                                 const float* __restrict__ e1w, const float* __restrict__ e2w) {
    int idx = blockIdx.x * 256 + threadIdx.x;
    if (idx < 8192) {
        int lane = idx & 31, g = lane >> 2, tq = lane & 3;
        int nt = (idx >> 5) & 63;
        int n = nt * 8 + g, k0 = ((idx >> 11) * 16) + 2 * tq;
        const float* w = nw1 + n * RR;
        g_w1f[idx] = make_uint2(pack_rn2(w[k0], w[k0 + 1]), pack_rn2(w[k0 + 8], w[k0 + 9]));
    } else if (idx < 16384) {
        int j = idx - 8192;
        int lane = j & 31, g = lane >> 2, tq = lane & 3;
        int nt = (j >> 5) & 7;
        int n = nt * 8 + g, k0 = ((j >> 8) * 16) + 2 * tq;
        const float* w = nw2 + n * HN;
        g_w2f[j] = make_uint2(pack_rn2(w[k0], w[k0 + 1]), pack_rn2(w[k0 + 8], w[k0 + 9]));
    } else if (idx < 16384 + 8704) {
        int j = idx - 16384;
        int lane = j & 31, g = lane >> 2, tq = lane & 3;
        int kc = (j >> 5) & 3, nt = j >> 7;
        int n = nt * 8 + g, k0 = kc * 16 + 2 * tq;
        const float* w;
        if (n < 512) {
            int m = n >> 4, inner = n & 15;
            w = (inner < 8) ? muw + (m * 8 + inner) * RR : sgw + (m * 8 + inner - 8) * RR;
        } else {
            w = alw + (n - 512) * RR;
        }
        g_hf[j] = make_uint2(pack_rn2(w[k0], w[k0 + 1]), pack_rn2(w[k0 + 8], w[k0 + 9]));
    } else if (idx < 16384 + 8704 + 1024) {
        int j = idx - 16384 - 8704;
        int lane = j & 31, g = lane >> 2, tq = lane & 3;
        int nt = j >> 5;
        int n = nt * 8 + g;
        g_e1f[j] = pack_rn2(e1w[n * XDIM + 2 * tq], e1w[n * XDIM + 2 * tq + 1]);
    } else if (idx < 16384 + 8704 + 1024 + 4096) {
        int j = idx - 16384 - 8704 - 1024;
        int lane = j & 31, g = lane >> 2, tq = lane & 3;
        int nt = (j >> 5) & 7, kc = j >> 8;
        int n = nt * 8 + g, k0 = kc * 16 + 2 * tq;
        const float* w = e2w + n * HE;
        g_e2f[j] = make_uint2(pack_rn2(w[k0], w[k0 + 1]), pack_rn2(w[k0 + 8], w[k0 + 9]));
    }
}

__global__ void init_kernel(const float* __restrict__ iw) {
    int idx = blockIdx.x * blockDim.x + threadIdx.x;
    if (idx < NN * RR) g_tmpAll[0][idx] = iw[idx & (RR - 1)];
}

// ---------------------------------------------------------------- encoder (bf16 mma)
// block = (l, 128 samples). layer1: x[128,8] @ w1T[8,256] (k8 mma), relu,
// layer2: h1[128,256] @ w2T[256,64] (k16 mma), fused per 32-col chunk.
__global__ __launch_bounds__(256) void enc_mma_kernel(const float* __restrict__ X,
        const float* __restrict__ b1e, const float* __restrict__ b2e) {
    __shared__ float sX[128][9];
    int tid = threadIdx.x;
    int wid = tid >> 5, lane = tid & 31;
    int g = lane >> 2, tq = lane & 3;
    int l = blockIdx.x & 15;
    int nb = (blockIdx.x >> 4) * 128;
    int r0 = wid * 16 + g, r1 = r0 + 8;

    // stage x in smem + write g_XT
    for (int v = tid; v < 1024; v += 256) {
        int row = v >> 3, xd = v & 7;
        float x = X[((size_t)(nb + row) * XDIM + xd) * LL + l];
        sX[row][xd] = x;
        g_XT[((size_t)l * NN + nb + row) * XDIM + xd] = x;
    }
    __syncthreads();

    uint32_t a0 = pack_rn2(sX[r0][2 * tq], sX[r0][2 * tq + 1]);
    uint32_t a1 = pack_rn2(sX[r1][2 * tq], sX[r1][2 * tq + 1]);

    float acc2[8][4];
#pragma unroll
    for (int nt = 0; nt < 8; nt++)
#pragma unroll
        for (int c = 0; c < 4; c++) acc2[nt][c] = 0.f;

#pragma unroll
    for (int c = 0; c < 8; c++) {   // 32-col chunk of h1
        float C1[4][4];
#pragma unroll
        for (int nt2 = 0; nt2 < 4; nt2++) {
#pragma unroll
            for (int q = 0; q < 4; q++) C1[nt2][q] = 0.f;
            uint32_t be = __ldg(g_e1f + (c * 4 + nt2) * 32 + lane);
            mma_bf16_k8(C1[nt2], a0, a1, be);
        }
        uint32_t A2[2][4];
#pragma unroll
        for (int j = 0; j < 2; j++) {
            int colA = c * 32 + j * 16 + 2 * tq;
            float ba0 = __ldg(b1e + colA), ba1 = __ldg(b1e + colA + 1);
            float bb0 = __ldg(b1e + colA + 8), bb1 = __ldg(b1e + colA + 9);
            A2[j][0] = pack_rn2(fmaxf(C1[2*j][0] + ba0, 0.f),   fmaxf(C1[2*j][1] + ba1, 0.f));
            A2[j][1] = pack_rn2(fmaxf(C1[2*j][2] + ba0, 0.f),   fmaxf(C1[2*j][3] + ba1, 0.f));
            A2[j][2] = pack_rn2(fmaxf(C1[2*j+1][0] + bb0, 0.f), fmaxf(C1[2*j+1][1] + bb1, 0.f));
            A2[j][3] = pack_rn2(fmaxf(C1[2*j+1][2] + bb0, 0.f), fmaxf(C1[2*j+1][3] + bb1, 0.f));
        }
#pragma unroll
        for (int j = 0; j < 2; j++) {
            int kc = c * 2 + j;
#pragma unroll
            for (int nt = 0; nt < 8; nt++) {
                uint2 bf = __ldg(g_e2f + (kc * 8 + nt) * 32 + lane);
                mma1(acc2[nt], A2[j], bf);
            }
        }
    }

    float* ob = g_enc + ((size_t)l * NN + nb) * DD;
#pragma unroll
    for (int nt = 0; nt < 8; nt++) {
        int col = nt * 8 + 2 * tq;
        float c0 = __ldg(b2e + col), c1 = __ldg(b2e + col + 1);
        *(float2*)(ob + (size_t)r0 * DD + col) = make_float2(acc2[nt][0] + c0, acc2[nt][1] + c1);
        *(float2*)(ob + (size_t)r1 * DD + col) = make_float2(acc2[nt][2] + c0, acc2[nt][3] + c1);
    }
}

// ---------------------------------------------------------------- recurrence update (single bf16 mma)
__global__ __launch_bounds__(256, 2) void update_mma_kernel(int t) {
    __shared__ float sTmp[128][68];
    int tid = threadIdx.x;
    int wid = tid >> 5, lane = tid & 31;
    int g = lane >> 2, tq = lane & 3;
    int sb = blockIdx.x * 128;
    int r0 = wid * 16 + g, r1 = r0 + 8;

    const float4* tin4 = (const float4*)(g_tmpAll[t - 1] + (size_t)sb * RR);
    for (int v = tid; v < 2048; v += 256) {
        int r = v >> 4, c = (v & 15) << 2;
        *(float4*)&sTmp[r][c] = tin4[v];
    }
    float e0[4][4], e1[4][4];
    {
        const float* ep0 = g_enc + ((size_t)(t - 1) * NN + sb + r0) * DD;
        const float* ep1 = g_enc + ((size_t)(t - 1) * NN + sb + r1) * DD;
#pragma unroll
        for (int q = 0; q < 4; q++) {
            float2 a = __ldg((const float2*)(ep0 + q * 16 + 2 * tq));
            float2 b = __ldg((const float2*)(ep0 + q * 16 + 2 * tq + 8));
            e0[q][0] = a.x; e0[q][1] = a.y; e0[q][2] = b.x; e0[q][3] = b.y;
            float2 c = __ldg((const float2*)(ep1 + q * 16 + 2 * tq));
            float2 d = __ldg((const float2*)(ep1 + q * 16 + 2 * tq + 8));
            e1[q][0] = c.x; e1[q][1] = c.y; e1[q][2] = d.x; e1[q][3] = d.y;
        }
    }
    __syncthreads();

    float acc[8][4];
#pragma unroll
    for (int nt = 0; nt < 8; nt++)
#pragma unroll
        for (int c = 0; c < 4; c++) acc[nt][c] = 0.f;

    const uint2* bfr = g_Bf2 + (size_t)(t - 1) * 65536 + lane;

    for (int i = 0; i < 64; i++) {
        float t0 = sTmp[r0][i];
        float t1 = sTmp[r1][i];
#pragma unroll
        for (int q = 0; q < 4; q++) {
            uint32_t a0 = pack_rn2(t0 * e0[q][0], t0 * e0[q][1]);
            uint32_t a1 = pack_rn2(t1 * e1[q][0], t1 * e1[q][1]);
            uint32_t a2 = pack_rn2(t0 * e0[q][2], t0 * e0[q][3]);
            uint32_t a3 = pack_rn2(t1 * e1[q][2], t1 * e1[q][3]);
            int ki = (i << 2) + q;
#pragma unroll
            for (int nt = 0; nt < 8; nt++) {
                uint2 bf = __ldg(bfr + (((ki << 3) + nt) << 5));
                mma_bf16(acc[nt], a0, a1, a2, a3, bf.x, bf.y);
            }
        }
    }

    float* ob = g_tmpAll[t] + (size_t)sb * RR;
#pragma unroll
    for (int nt = 0; nt < 8; nt++) {
        int col = nt * 8 + 2 * tq;
        *(float2*)(ob + (size_t)r0 * RR + col) = make_float2(acc[nt][0], acc[nt][1]);
        *(float2*)(ob + (size_t)r1 * RR + col) = make_float2(acc[nt][2], acc[nt][3]);
    }
}

// ---------------------------------------------------------------- phi (all 16 steps, bf16 mma chain)
__global__ __launch_bounds__(256) void phi_kernel(
        const float* __restrict__ b1, const float* __restrict__ b2,
        const float* __restrict__ mub, const float* __restrict__ sgb,
        const float* __restrict__ alb) {
    __shared__ float sT[64 * 132];   // tmp transposed; later reused as alpha bcast [128][33]
    __shared__ float sred[256];
    int tid = threadIdx.x;
    int wid = tid >> 5, lane = tid & 31;
    int g = lane >> 2, tq = lane & 3;
    int t = blockIdx.y;
    int bs = blockIdx.x * 128;
    int r0 = wid * 16 + g, r1 = r0 + 8;

    const float4* t4 = (const float4*)(g_tmpAll[t] + (size_t)bs * RR);
    float sq = 0.f;
    for (int v = tid; v < 2048; v += 256) {
        int s = v >> 4, c = (v & 15) << 2;
        float4 a = t4[v];
        sq += a.x * a.x + a.y * a.y + a.z * a.z + a.w * a.w;
        sT[(c + 0) * 132 + s] = a.x; sT[(c + 1) * 132 + s] = a.y;
        sT[(c + 2) * 132 + s] = a.z; sT[(c + 3) * 132 + s] = a.w;
    }
    sred[tid] = sq;
    __syncthreads();
    for (int off = 128; off > 0; off >>= 1) {
        if (tid < off) sred[tid] += sred[tid + off];
        __syncthreads();
    }
    if (tid == 0) g_npart[t * PHI_B + blockIdx.x] = sred[0];

    uint32_t A1[4][4];
#pragma unroll
    for (int ki = 0; ki < 4; ki++) {
        int k0 = ki * 16 + 2 * tq;
        A1[ki][0] = pack_rn2(sT[k0 * 132 + r0], sT[(k0 + 1) * 132 + r0]);
        A1[ki][1] = pack_rn2(sT[k0 * 132 + r1], sT[(k0 + 1) * 132 + r1]);
        A1[ki][2] = pack_rn2(sT[(k0 + 8) * 132 + r0], sT[(k0 + 9) * 132 + r0]);
        A1[ki][3] = pack_rn2(sT[(k0 + 8) * 132 + r1], sT[(k0 + 9) * 132 + r1]);
    }
    __syncthreads();   // sT reads done -> safe to reuse

    float acc2[8][4];
#pragma unroll
    for (int nt = 0; nt < 8; nt++)
#pragma unroll
        for (int c = 0; c < 4; c++) acc2[nt][c] = 0.f;

    for (int c = 0; c < 8; c++) {
        float C1[8][4];
#pragma unroll
        for (int nt2 = 0; nt2 < 8; nt2++) {
#pragma unroll
            for (int q = 0; q < 4; q++) C1[nt2][q] = 0.f;
#pragma unroll
            for (int ki = 0; ki < 4; ki++) {
                uint2 bf = __ldg(g_w1f + (ki * 64 + c * 8 + nt2) * 32 + lane);
                mma1(C1[nt2], A1[ki], bf);
            }
        }
        uint32_t A2[4][4];
#pragma unroll
        for (int j = 0; j < 4; j++) {
            int colA = c * 64 + j * 16 + 2 * tq;
            float ba0 = __ldg(b1 + colA), ba1 = __ldg(b1 + colA + 1);
            float bb0 = __ldg(b1 + colA + 8), bb1 = __ldg(b1 + colA + 9);
            A2[j][0] = pack_rn2(fmaxf(C1[2*j][0] + ba0, 0.f),   fmaxf(C1[2*j][1] + ba1, 0.f));
            A2[j][1] = pack_rn2(fmaxf(C1[2*j][2] + ba0, 0.f),   fmaxf(C1[2*j][3] + ba1, 0.f));
            A2[j][2] = pack_rn2(fmaxf(C1[2*j+1][0] + bb0, 0.f), fmaxf(C1[2*j+1][1] + bb1, 0.f));
            A2[j][3] = pack_rn2(fmaxf(C1[2*j+1][2] + bb0, 0.f), fmaxf(C1[2*j+1][3] + bb1, 0.f));
        }
#pragma unroll
        for (int j = 0; j < 4; j++) {
            int kc = c * 4 + j;
#pragma unroll
            for (int nt = 0; nt < 8; nt++) {
                uint2 bf = __ldg(g_w2f + (kc * 8 + nt) * 32 + lane);
                mma1(acc2[nt], A2[j], bf);
            }
        }
    }

    uint32_t A3[4][4];
#pragma unroll
    for (int j = 0; j < 4; j++) {
        int colA = j * 16 + 2 * tq;
        float ba0 = __ldg(b2 + colA), ba1 = __ldg(b2 + colA + 1);
        float bb0 = __ldg(b2 + colA + 8), bb1 = __ldg(b2 + colA + 9);
        A3[j][0] = pack_rn2(fmaxf(acc2[2*j][0] + ba0, 0.f),   fmaxf(acc2[2*j][1] + ba1, 0.f));
        A3[j][1] = pack_rn2(fmaxf(acc2[2*j][2] + ba0, 0.f),   fmaxf(acc2[2*j][3] + ba1, 0.f));
        A3[j][2] = pack_rn2(fmaxf(acc2[2*j+1][0] + bb0, 0.f), fmaxf(acc2[2*j+1][1] + bb1, 0.f));
        A3[j][3] = pack_rn2(fmaxf(acc2[2*j+1][2] + bb0, 0.f), fmaxf(acc2[2*j+1][3] + bb1, 0.f));
    }

    float alp[4][4];
#pragma unroll
    for (int nt = 0; nt < 4; nt++) {
#pragma unroll
        for (int q = 0; q < 4; q++) alp[nt][q] = 0.f;
#pragma unroll
        for (int kc = 0; kc < 4; kc++) {
            uint2 bf = __ldg(g_hf + ((64 + nt) * 4 + kc) * 32 + lane);
            mma1(alp[nt], A3[kc], bf);
        }
        float a0b = __ldg(alb + nt * 8 + 2 * tq), a1b = __ldg(alb + nt * 8 + 2 * tq + 1);
        alp[nt][0] += a0b; alp[nt][1] += a1b; alp[nt][2] += a0b; alp[nt][3] += a1b;
    }
    float* sAl = sT;
#pragma unroll
    for (int nt = 0; nt < 4; nt++) {
        sAl[r0 * 33 + nt * 8 + 2 * tq]     = alp[nt][0];
        sAl[r0 * 33 + nt * 8 + 2 * tq + 1] = alp[nt][1];
        sAl[r1 * 33 + nt * 8 + 2 * tq]     = alp[nt][2];
        sAl[r1 * 33 + nt * 8 + 2 * tq + 1] = alp[nt][3];
    }
    __syncwarp();

    float Mg = -3.4e38f, Sg = 0.f, Mh = -3.4e38f, Sh = 0.f;
#pragma unroll
    for (int nt = 0; nt < 4; nt++) {
        lse_upd(Mg, Sg, alp[nt][0]); lse_upd(Mg, Sg, alp[nt][1]);
        lse_upd(Mh, Sh, alp[nt][2]); lse_upd(Mh, Sh, alp[nt][3]);
    }
#pragma unroll
    for (int dd = 1; dd < 4; dd <<= 1) {
        float Mo = __shfl_xor_sync(0xffffffffu, Mg, dd);
        float So = __shfl_xor_sync(0xffffffffu, Sg, dd);
        float Mn = fmaxf(Mg, Mo);
        Sg = Sg * __expf(Mg - Mn) + So * __expf(Mo - Mn); Mg = Mn;
        Mo = __shfl_xor_sync(0xffffffffu, Mh, dd);
        So = __shfl_xor_sync(0xffffffffu, Sh, dd);
        Mn = fmaxf(Mh, Mo);
        Sh = Sh * __expf(Mh - Mn) + So * __expf(Mo - Mn); Mh = Mn;
    }

    const float* xp = g_XT + ((size_t)t * NN + bs) * XDIM;
    float2 xa = *(const float2*)(xp + r0 * XDIM + 2 * tq);
    float2 xb = *(const float2*)(xp + r1 * XDIM + 2 * tq);

    float Mtg = -3.4e38f, Stg = 0.f, Mth = -3.4e38f, Sth = 0.f;
#pragma unroll 4
    for (int m = 0; m < 32; m++) {
        float Cm[4] = {0.f, 0.f, 0.f, 0.f}, Cs[4] = {0.f, 0.f, 0.f, 0.f};
#pragma unroll
        for (int kc = 0; kc < 4; kc++) {
            uint2 bm = __ldg(g_hf + ((2 * m) * 4 + kc) * 32 + lane);
            mma1(Cm, A3[kc], bm);
            uint2 bv = __ldg(g_hf + ((2 * m + 1) * 4 + kc) * 32 + lane);
            mma1(Cs, A3[kc], bv);
        }
        float mb0 = __ldg(mub + m * 8 + 2 * tq), mb1 = __ldg(mub + m * 8 + 2 * tq + 1);
        float sb0 = __ldg(sgb + m * 8 + 2 * tq), sb1 = __ldg(sgb + m * 8 + 2 * tq + 1);
        float l0 = Cs[0] + sb0, l1 = Cs[1] + sb1, l2 = Cs[2] + sb0, l3 = Cs[3] + sb1;
        float z0 = (xa.x - (Cm[0] + mb0)) * __expf(-l0);
        float z1 = (xa.y - (Cm[1] + mb1)) * __expf(-l1);
        float z2 = (xb.x - (Cm[2] + mb0)) * __expf(-l2);
        float z3 = (xb.y - (Cm[3] + mb1)) * __expf(-l3);
        float cg = -0.5f * z0 * z0 - l0 - 0.5f * z1 * z1 - l1;
        float ch = -0.5f * z2 * z2 - l2 - 0.5f * z3 * z3 - l3;
        cg += __shfl_xor_sync(0xffffffffu, cg, 1);
        cg += __shfl_xor_sync(0xffffffffu, cg, 2);
        ch += __shfl_xor_sync(0xffffffffu, ch, 1);
        ch += __shfl_xor_sync(0xffffffffu, ch, 2);
        cg += -0.5f * XDIM * LOG2PI_F;
        ch += -0.5f * XDIM * LOG2PI_F;
        float ag = sAl[r0 * 33 + m], ah = sAl[r1 * 33 + m];
        lse_upd(Mtg, Stg, ag + cg);
        lse_upd(Mth, Sth, ah + ch);
    }
    if (tq == 0) {
        g_res[t][bs + r0] = (Mtg + __logf(Stg)) - (Mg + __logf(Sg));
        g_res[t][bs + r1] = (Mth + __logf(Sth)) - (Mh + __logf(Sh));
    }
}

// ---------------------------------------------------------------- finish
__global__ void finish_kernel(float* __restrict__ out, int out_n) {
    int idx = blockIdx.x * 256 + threadIdx.x;
    if (idx < NN) {
        float s = 0.f;
#pragma unroll
        for (int t = 0; t < LL; t++) s += g_res[t][idx];
        out[idx] = s;
    } else if (idx < out_n) {
        out[idx] = 0.f;
    }
}

__global__ void norm_kernel(float* __restrict__ out, int out_n) {
    __shared__ float red[256];
    int tid = threadIdx.x;
    float s = 0.f;
    for (int v = tid; v < LL * PHI_B; v += 256) s += g_npart[v];
    red[tid] = s;
    __syncthreads();
    for (int off = 128; off > 0; off >>= 1) {
        if (tid < off) red[tid] += red[tid + off];
        __syncthreads();
    }
    if (tid == 0) out[out_n - 1] = red[0];
}

// ---------------------------------------------------------------- launch
extern "C" void kernel_launch(void* const* d_in, const int* in_sizes, int n_in,
                              void* d_out, int out_size) {
    const float* X    = (const float*)d_in[0];
    const float* iw   = (const float*)d_in[1];
    const float* cores= (const float*)d_in[2];
    const float* e1w  = (const float*)d_in[3];
    const float* e1b  = (const float*)d_in[4];
    const float* e2w  = (const float*)d_in[5];
    const float* e2b  = (const float*)d_in[6];
    const float* nw1  = (const float*)d_in[7];
    const float* nb1  = (const float*)d_in[8];
    const float* nw2  = (const float*)d_in[9];
    const float* nb2  = (const float*)d_in[10];
    const float* muw  = (const float*)d_in[11];
    const float* mub  = (const float*)d_in[12];
    const float* sgw  = (const float*)d_in[13];
    const float* sgb  = (const float*)d_in[14];
    const float* alw  = (const float*)d_in[15];
    const float* alb  = (const float*)d_in[16];
    float* out = (float*)d_out;

    prep_bfrag_kernel<<<((LL - 1) * 256 * 8 * 32 + 255) / 256, 256>>>(cores);
    prep_stage_frags<<<(16384 + 8704 + 1024 + 4096 + 255) / 256, 256>>>(nw1, nw2, muw, sgw, alw, e1w, e2w);
    init_kernel<<<(NN * RR + 255) / 256, 256>>>(iw);
    enc_mma_kernel<<<(LL * NN) / 128, 256>>>(X, e1b, e2b);

    for (int t = 1; t < LL; t++)
        update_mma_kernel<<<NN / 128, 256>>>(t);

    dim3 pg(PHI_B, LL);
    phi_kernel<<<pg, 256>>>(nb1, nb2, mub, sgb, alb);

    finish_kernel<<<(out_size + 255) / 256, 256>>>(out, out_size);
    norm_kernel<<<1, 256>>>(out, out_size);
}